// round 3
// baseline (speedup 1.0000x reference)
#include <cuda_runtime.h>
#include <cuda_bf16.h>
#include <math.h>

// ---------------------------------------------------------------------------
// Problem constants (all static for this shape)
// ---------------------------------------------------------------------------
#define BATCH   32
#define HIMG    56
#define WIMG    56
#define CDIM    384
#define LTOK    (HIMG*WIMG)          // 3136
#define NHEADS  12
#define HD      32
#define WS      7
#define NWIN_T  49                   // tokens per window
#define SHIFT   3
#define NWX     8                    // windows per row
#define NWIN    64                   // windows per image
#define BN      (BATCH*NWIN)         // 2048 windows total
#define MTOK    (BN*NWIN_T)          // 100352 tokens
#define HID     1536

// ---------------------------------------------------------------------------
// Scratch (device globals; no runtime allocation allowed)
// ---------------------------------------------------------------------------
__device__ float g_win [(size_t)MTOK * CDIM];    // LN1+shift+partition output
__device__ float g_qkv [(size_t)MTOK * 3 * CDIM];// qkv GEMM output
__device__ float g_attn[(size_t)MTOK * CDIM];    // attention output (window order)
__device__ float g_proj[(size_t)MTOK * CDIM];    // proj GEMM output (window order)
__device__ float g_y   [(size_t)MTOK * CDIM];    // x + attn branch (natural order)
__device__ float g_h2  [(size_t)MTOK * CDIM];    // LN2 output
__device__ float g_mlp1[(size_t)MTOK * HID];     // fc1+gelu output

// ---------------------------------------------------------------------------
// LayerNorm (+ optional shift/window-partition gather)
// one block per output token, 128 threads, 3 channels per thread
// ---------------------------------------------------------------------------
__global__ __launch_bounds__(128)
void ln_kernel(const float* __restrict__ x, const float* __restrict__ gam,
               const float* __restrict__ bet, float* __restrict__ out,
               int shifted)
{
    int tr = blockIdx.x;            // output row
    int src;
    if (shifted) {
        int bn = tr / NWIN_T;
        int n  = tr - bn * NWIN_T;
        int b  = bn / NWIN;
        int wi = bn - b * NWIN;
        int wy = wi / NWX, wx = wi - wy * NWX;
        int r  = n / WS,   cc = n - r * WS;
        int hs = (wy * WS + r  + SHIFT) % HIMG;
        int ws2= (wx * WS + cc + SHIFT) % WIMG;
        src = b * LTOK + hs * WIMG + ws2;
    } else {
        src = tr;
    }
    const float* xin = x + (size_t)src * CDIM;
    int tid = threadIdx.x;
    float v0 = xin[tid], v1 = xin[tid + 128], v2 = xin[tid + 256];
    float s  = v0 + v1 + v2;
    float ss = v0*v0 + v1*v1 + v2*v2;
    #pragma unroll
    for (int o = 16; o > 0; o >>= 1) {
        s  += __shfl_down_sync(0xffffffffu, s,  o);
        ss += __shfl_down_sync(0xffffffffu, ss, o);
    }
    __shared__ float red[8];
    __shared__ float mb[2];
    int w = tid >> 5, l = tid & 31;
    if (l == 0) { red[w] = s; red[4 + w] = ss; }
    __syncthreads();
    if (tid == 0) {
        float S  = red[0] + red[1] + red[2] + red[3];
        float SS = red[4] + red[5] + red[6] + red[7];
        float mean = S * (1.0f / CDIM);
        float var  = SS * (1.0f / CDIM) - mean * mean;
        mb[0] = mean;
        mb[1] = rsqrtf(var + 1e-5f);
    }
    __syncthreads();
    float mean = mb[0], rstd = mb[1];
    float* o = out + (size_t)tr * CDIM;
    o[tid]       = (v0 - mean) * rstd * gam[tid]       + bet[tid];
    o[tid + 128] = (v1 - mean) * rstd * gam[tid + 128] + bet[tid + 128];
    o[tid + 256] = (v2 - mean) * rstd * gam[tid + 256] + bet[tid + 256];
}

// ---------------------------------------------------------------------------
// SGEMM: C[M,N] = A[M,K] @ B[K,N] (+bias, optional GELU / residual)
// 128x128 tile, BK=8, 256 threads, 8x8 register tiles. M,N % 128 == 0, K % 8 == 0.
// EPI: 0 = bias, 1 = bias + exact GELU, 2 = bias + residual add
// ---------------------------------------------------------------------------
template <int EPI>
__global__ __launch_bounds__(256)
void sgemm_kernel(const float* __restrict__ A, const float* __restrict__ B,
                  const float* __restrict__ bias, const float* __restrict__ res,
                  float* __restrict__ C, int M, int N, int K)
{
    __shared__ __align__(16) float As[8][128];
    __shared__ __align__(16) float Bs[8][128];

    int tid = threadIdx.x;
    int m0 = blockIdx.y * 128;
    int n0 = blockIdx.x * 128;
    int tx = tid & 15, ty = tid >> 4;

    int arow  = tid >> 1;          // 0..127
    int acol4 = (tid & 1) * 4;     // 0 or 4
    int brow  = tid >> 5;          // 0..7
    int bcol4 = (tid & 31) * 4;    // 0..124

    const float* Aptr = A + (size_t)(m0 + arow) * K + acol4;
    const float* Bptr = B + (size_t)brow * N + n0 + bcol4;

    float acc[8][8];
    #pragma unroll
    for (int i = 0; i < 8; i++)
        #pragma unroll
        for (int j = 0; j < 8; j++) acc[i][j] = 0.0f;

    for (int k0 = 0; k0 < K; k0 += 8) {
        float4 av = *(const float4*)(Aptr + k0);
        float4 bv = *(const float4*)(Bptr + (size_t)k0 * N);
        As[acol4 + 0][arow] = av.x;
        As[acol4 + 1][arow] = av.y;
        As[acol4 + 2][arow] = av.z;
        As[acol4 + 3][arow] = av.w;
        *(float4*)&Bs[brow][bcol4] = bv;
        __syncthreads();
        #pragma unroll
        for (int kk = 0; kk < 8; kk++) {
            float4 a0 = *(const float4*)&As[kk][ty * 8];
            float4 a1 = *(const float4*)&As[kk][ty * 8 + 4];
            float4 b0 = *(const float4*)&Bs[kk][tx * 8];
            float4 b1 = *(const float4*)&Bs[kk][tx * 8 + 4];
            float a[8] = {a0.x, a0.y, a0.z, a0.w, a1.x, a1.y, a1.z, a1.w};
            float b[8] = {b0.x, b0.y, b0.z, b0.w, b1.x, b1.y, b1.z, b1.w};
            #pragma unroll
            for (int i = 0; i < 8; i++)
                #pragma unroll
                for (int j = 0; j < 8; j++) acc[i][j] += a[i] * b[j];
        }
        __syncthreads();
    }

    float bv[8];
    #pragma unroll
    for (int j = 0; j < 8; j++) bv[j] = bias[n0 + tx * 8 + j];

    #pragma unroll
    for (int i = 0; i < 8; i++) {
        size_t row = (size_t)(m0 + ty * 8 + i);
        float* crow = C + row * N + n0 + tx * 8;
        float outv[8];
        #pragma unroll
        for (int j = 0; j < 8; j++) {
            float v = acc[i][j] + bv[j];
            if (EPI == 1) v = 0.5f * v * (1.0f + erff(v * 0.70710678118654752f));
            if (EPI == 2) v += res[row * N + n0 + tx * 8 + j];
            outv[j] = v;
        }
        *(float4*)crow       = make_float4(outv[0], outv[1], outv[2], outv[3]);
        *(float4*)(crow + 4) = make_float4(outv[4], outv[5], outv[6], outv[7]);
    }
}

// ---------------------------------------------------------------------------
// Windowed attention: one block per (window, head). N=49, hd=32.
// ---------------------------------------------------------------------------
__global__ __launch_bounds__(128)
void attn_kernel(const float* __restrict__ qkv, const float* __restrict__ mask,
                 const float* __restrict__ rpb, float* __restrict__ outp)
{
    __shared__ float Qs[NWIN_T * 32];
    __shared__ float Ks[NWIN_T * 33];   // padded stride: kills 32-way conflict
    __shared__ float Vs[NWIN_T * 32];
    __shared__ float Ss[NWIN_T * NWIN_T];

    int bn = blockIdx.x;
    int h  = blockIdx.y;
    int tid = threadIdx.x;
    const float scale = 0.1767766952966369f;   // 32^-0.5

    size_t base = (size_t)bn * NWIN_T * (3 * CDIM) + h * HD;
    for (int idx = tid; idx < NWIN_T * 32; idx += 128) {
        int n = idx >> 5, d = idx & 31;
        size_t p = base + (size_t)n * (3 * CDIM) + d;
        Qs[idx]        = qkv[p] * scale;
        Ks[n * 33 + d] = qkv[p + CDIM];
        Vs[idx]        = qkv[p + 2 * CDIM];
    }
    __syncthreads();

    const float* mw = mask + (bn & (NWIN - 1)) * (NWIN_T * NWIN_T);
    for (int pix = tid; pix < NWIN_T * NWIN_T; pix += 128) {
        int n = pix / NWIN_T, m = pix - n * NWIN_T;
        float acc = 0.0f;
        #pragma unroll
        for (int d = 0; d < 32; d++) acc += Qs[n * 32 + d] * Ks[m * 33 + d];
        int r1 = n / WS, c1 = n - r1 * WS;
        int r2 = m / WS, c2 = m - r2 * WS;
        int rel = (r1 - r2 + WS - 1) * (2 * WS - 1) + (c1 - c2 + WS - 1);
        Ss[pix] = acc + rpb[rel * NHEADS + h] + mw[pix];
    }
    __syncthreads();

    if (tid < NWIN_T) {
        float* row = Ss + tid * NWIN_T;
        float mx = -1e30f;
        #pragma unroll 7
        for (int m = 0; m < NWIN_T; m++) mx = fmaxf(mx, row[m]);
        float sum = 0.0f;
        #pragma unroll 7
        for (int m = 0; m < NWIN_T; m++) { float e = __expf(row[m] - mx); row[m] = e; sum += e; }
        float inv = 1.0f / sum;
        #pragma unroll 7
        for (int m = 0; m < NWIN_T; m++) row[m] *= inv;
    }
    __syncthreads();

    for (int idx = tid; idx < NWIN_T * 32; idx += 128) {
        int n = idx >> 5, d = idx & 31;
        float acc = 0.0f;
        #pragma unroll 7
        for (int m = 0; m < NWIN_T; m++) acc += Ss[n * NWIN_T + m] * Vs[m * 32 + d];
        outp[(size_t)(bn * NWIN_T + n) * CDIM + h * HD + d] = acc;
    }
}

// ---------------------------------------------------------------------------
// Window-reverse + reverse roll + residual:  y = x + unshuffle(proj)
// ---------------------------------------------------------------------------
__global__ __launch_bounds__(256)
void merge_kernel(const float* __restrict__ x, const float* __restrict__ proj,
                  float* __restrict__ y)
{
    size_t e = (size_t)blockIdx.x * blockDim.x + threadIdx.x;
    const size_t TOT = (size_t)MTOK * CDIM;
    if (e >= TOT) return;
    int row = (int)(e / CDIM), c = (int)(e - (size_t)row * CDIM);
    int b = row / LTOK, pos = row - b * LTOK;
    int i = pos / WIMG, j = pos - i * WIMG;
    int ii = (i + HIMG - SHIFT) % HIMG;
    int jj = (j + WIMG - SHIFT) % WIMG;
    int tr = (b * NWIN + (ii / WS) * NWX + (jj / WS)) * NWIN_T + (ii % WS) * WS + (jj % WS);
    y[e] = x[e] + proj[(size_t)tr * CDIM + c];
}

// ---------------------------------------------------------------------------
// Launch
// ---------------------------------------------------------------------------
extern "C" void kernel_launch(void* const* d_in, const int* in_sizes, int n_in,
                              void* d_out, int out_size)
{
    const float* x        = (const float*)d_in[0];
    const float* attnmask = (const float*)d_in[1];
    const float* norm1_g  = (const float*)d_in[2];
    const float* norm1_b  = (const float*)d_in[3];
    const float* qkv_w    = (const float*)d_in[4];
    const float* qkv_b    = (const float*)d_in[5];
    const float* rpb      = (const float*)d_in[6];
    const float* proj_w   = (const float*)d_in[7];
    const float* proj_b   = (const float*)d_in[8];
    const float* norm2_g  = (const float*)d_in[9];
    const float* norm2_b  = (const float*)d_in[10];
    const float* fc1_w    = (const float*)d_in[11];
    const float* fc1_b    = (const float*)d_in[12];
    const float* fc2_w    = (const float*)d_in[13];
    const float* fc2_b    = (const float*)d_in[14];
    (void)in_sizes; (void)n_in; (void)out_size;

    float *win, *qkvbuf, *attnb, *projb, *y, *h2, *mlp1;
    cudaGetSymbolAddress((void**)&win,    g_win);
    cudaGetSymbolAddress((void**)&qkvbuf, g_qkv);
    cudaGetSymbolAddress((void**)&attnb,  g_attn);
    cudaGetSymbolAddress((void**)&projb,  g_proj);
    cudaGetSymbolAddress((void**)&y,      g_y);
    cudaGetSymbolAddress((void**)&h2,     g_h2);
    cudaGetSymbolAddress((void**)&mlp1,   g_mlp1);

    // 1. LN1 + shift + window partition
    ln_kernel<<<MTOK, 128>>>(x, norm1_g, norm1_b, win, 1);

    // 2. QKV GEMM: (100352 x 384) @ (384 x 1152)
    sgemm_kernel<0><<<dim3(1152 / 128, MTOK / 128), 256>>>(
        win, qkv_w, qkv_b, nullptr, qkvbuf, MTOK, 3 * CDIM, CDIM);

    // 3. Windowed attention
    attn_kernel<<<dim3(BN, NHEADS), 128>>>(qkvbuf, attnmask, rpb, attnb);

    // 4. proj GEMM: (100352 x 384) @ (384 x 384)
    sgemm_kernel<0><<<dim3(384 / 128, MTOK / 128), 256>>>(
        attnb, proj_w, proj_b, nullptr, projb, MTOK, CDIM, CDIM);

    // 5. window reverse + roll + residual
    merge_kernel<<<(MTOK * CDIM + 255) / 256, 256>>>(x, projb, y);

    // 6. LN2
    ln_kernel<<<MTOK, 128>>>(y, norm2_g, norm2_b, h2, 0);

    // 7. fc1 + GELU: (100352 x 384) @ (384 x 1536)
    sgemm_kernel<1><<<dim3(HID / 128, MTOK / 128), 256>>>(
        h2, fc1_w, fc1_b, nullptr, mlp1, MTOK, HID, CDIM);

    // 8. fc2 + residual: (100352 x 1536) @ (1536 x 384) -> d_out
    sgemm_kernel<2><<<dim3(384 / 128, MTOK / 128), 256>>>(
        mlp1, fc2_w, fc2_b, y, (float*)d_out, MTOK, CDIM, HID);
}

// round 5
// speedup vs baseline: 1.6984x; 1.6984x over previous
#include <cuda_runtime.h>
#include <cuda_bf16.h>
#include <math.h>
#include <stdint.h>

// ---------------------------------------------------------------------------
// Problem constants
// ---------------------------------------------------------------------------
#define BATCH   32
#define HIMG    56
#define WIMG    56
#define CDIM    384
#define LTOK    (HIMG*WIMG)          // 3136
#define NHEADS  12
#define HD      32
#define WS      7
#define NWIN_T  49
#define SHIFT   3
#define NWX     8
#define NWIN    64
#define BN      (BATCH*NWIN)         // 2048 windows
#define MTOK    (BN*NWIN_T)          // 100352 tokens
#define HID     1536

// ---------------------------------------------------------------------------
// Scratch (device globals)
// ---------------------------------------------------------------------------
__device__ float          g_qkv [(size_t)MTOK * 3 * CDIM];
__device__ float          g_proj[(size_t)MTOK * CDIM];
__device__ float          g_y   [(size_t)MTOK * CDIM];
__device__ __nv_bfloat16  g_win_h[(size_t)MTOK * CDIM];
__device__ __nv_bfloat16  g_win_l[(size_t)MTOK * CDIM];
__device__ __nv_bfloat16  g_att_h[(size_t)MTOK * CDIM];
__device__ __nv_bfloat16  g_att_l[(size_t)MTOK * CDIM];
__device__ __nv_bfloat16  g_h2_h [(size_t)MTOK * CDIM];
__device__ __nv_bfloat16  g_h2_l [(size_t)MTOK * CDIM];
__device__ __nv_bfloat16  g_mlp_h[(size_t)MTOK * HID];
__device__ __nv_bfloat16  g_mlp_l[(size_t)MTOK * HID];
// transposed + split weights: Wt[N][K]
__device__ __nv_bfloat16  g_wq_h[3*CDIM*CDIM], g_wq_l[3*CDIM*CDIM];
__device__ __nv_bfloat16  g_wp_h[CDIM*CDIM],   g_wp_l[CDIM*CDIM];
__device__ __nv_bfloat16  g_w1_h[HID*CDIM],    g_w1_l[HID*CDIM];
__device__ __nv_bfloat16  g_w2_h[CDIM*HID],    g_w2_l[CDIM*HID];

// ---------------------------------------------------------------------------
// Helpers
// ---------------------------------------------------------------------------
static __device__ __forceinline__ uint32_t s2u(const void* p) {
    return (uint32_t)__cvta_generic_to_shared(p);
}
static __device__ __forceinline__ void split_store(__nv_bfloat16* ph, __nv_bfloat16* pl,
                                                   size_t idx, float v) {
    __nv_bfloat16 h = __float2bfloat16(v);
    ph[idx] = h;
    pl[idx] = __float2bfloat16(v - __bfloat162float(h));
}
static __device__ __forceinline__ void ldm4(uint32_t& d0, uint32_t& d1, uint32_t& d2,
                                            uint32_t& d3, uint32_t a) {
    asm volatile("ldmatrix.sync.aligned.m8n8.x4.shared.b16 {%0,%1,%2,%3},[%4];"
                 : "=r"(d0), "=r"(d1), "=r"(d2), "=r"(d3) : "r"(a));
}
static __device__ __forceinline__ void mma16816(float* c, const uint32_t* a, const uint32_t* b) {
    asm volatile("mma.sync.aligned.m16n8k16.row.col.f32.bf16.bf16.f32 "
                 "{%0,%1,%2,%3},{%4,%5,%6,%7},{%8,%9},{%0,%1,%2,%3};"
                 : "+f"(c[0]), "+f"(c[1]), "+f"(c[2]), "+f"(c[3])
                 : "r"(a[0]), "r"(a[1]), "r"(a[2]), "r"(a[3]), "r"(b[0]), "r"(b[1]));
}

// ---------------------------------------------------------------------------
// HMMA GEMM: C[M,N] = (Ah+Al)[M,K] @ (Bh+Bl)[N,K]^T  (bf16x3 compensated)
// 128x128 block tile, BK=32, 8 warps (2x4), warp tile 64x32, double-buffered.
// EPI 0: fp32 out + bias | 1: bias+GELU -> bf16 hi/lo | 2: bias+residual -> fp32
// ---------------------------------------------------------------------------
#define SMS      40                       // smem row stride (bf16 elems)
#define TILE_B   (128*SMS*2)              // 10240 bytes per tile
#define STAGE_B  (4*TILE_B)               // Ah,Al,Bh,Bl
#define GEMM_SMEM (2*STAGE_B)             // 81920 bytes

template <int EPI>
__global__ __launch_bounds__(256)
void mma_gemm(const __nv_bfloat16* __restrict__ Ah, const __nv_bfloat16* __restrict__ Al,
              const __nv_bfloat16* __restrict__ Bh, const __nv_bfloat16* __restrict__ Bl,
              const float* __restrict__ bias, const float* __restrict__ res,
              float* __restrict__ Cf, __nv_bfloat16* __restrict__ Ch,
              __nv_bfloat16* __restrict__ Cl, int N, int K)
{
    extern __shared__ char sm[];
    const int tid  = threadIdx.x, lane = tid & 31, warp = tid >> 5;
    const int m0 = blockIdx.y * 128, n0 = blockIdx.x * 128;
    const int wm = (warp >> 2) * 64, wn = (warp & 3) * 32;

    // -- global prefetch setup: each thread owns rows r0 and r0+64, cols c0..c0+7
    const int r0 = tid >> 2, c0 = (tid & 3) * 8;
    const __nv_bfloat16* pAh = Ah + (size_t)(m0 + r0) * K + c0;
    const __nv_bfloat16* pAl = Al + (size_t)(m0 + r0) * K + c0;
    const __nv_bfloat16* pBh = Bh + (size_t)(n0 + r0) * K + c0;
    const __nv_bfloat16* pBl = Bl + (size_t)(n0 + r0) * K + c0;
    const size_t rstep = (size_t)64 * K;
    const uint32_t so0 = (uint32_t)(r0 * SMS + c0) * 2;
    const uint32_t so1 = (uint32_t)((r0 + 64) * SMS + c0) * 2;

    uint4 gv[8];
    const uint32_t smb = s2u(sm);

    auto load_g = [&](int k0) {
        gv[0] = *(const uint4*)(pAh + k0);  gv[1] = *(const uint4*)(pAh + rstep + k0);
        gv[2] = *(const uint4*)(pAl + k0);  gv[3] = *(const uint4*)(pAl + rstep + k0);
        gv[4] = *(const uint4*)(pBh + k0);  gv[5] = *(const uint4*)(pBh + rstep + k0);
        gv[6] = *(const uint4*)(pBl + k0);  gv[7] = *(const uint4*)(pBl + rstep + k0);
    };
    auto store_s = [&](int s) {
        char* b = sm + s * STAGE_B;
        *(uint4*)(b + so0)              = gv[0];
        *(uint4*)(b + so1)              = gv[1];
        *(uint4*)(b + TILE_B + so0)     = gv[2];
        *(uint4*)(b + TILE_B + so1)     = gv[3];
        *(uint4*)(b + 2*TILE_B + so0)   = gv[4];
        *(uint4*)(b + 2*TILE_B + so1)   = gv[5];
        *(uint4*)(b + 3*TILE_B + so0)   = gv[6];
        *(uint4*)(b + 3*TILE_B + so1)   = gv[7];
    };

    float acc[4][4][4];
    #pragma unroll
    for (int i = 0; i < 4; i++)
        #pragma unroll
        for (int j = 0; j < 4; j++)
            #pragma unroll
            for (int k = 0; k < 4; k++) acc[i][j][k] = 0.0f;

    // ldmatrix lane addressing
    const int tsel = lane >> 3, rlo = lane & 7;
    const uint32_t aoff = (uint32_t)((wm + rlo + (tsel & 1) * 8) * SMS + (tsel >> 1) * 8) * 2;
    const uint32_t boff = (uint32_t)((wn + rlo + (tsel >> 1) * 8) * SMS + (tsel & 1) * 8) * 2;

    const int nch = K >> 5;
    load_g(0);
    store_s(0);

    for (int i = 0; i < nch; i++) {
        __syncthreads();
        if (i + 1 < nch) load_g((i + 1) << 5);

        const uint32_t sb  = smb + (i & 1) * STAGE_B;
        #pragma unroll
        for (int kst = 0; kst < 2; kst++) {
            uint32_t ah[4][4], al[4][4], bh[4][2], bl[4][2];
            #pragma unroll
            for (int mf = 0; mf < 4; mf++) {
                ldm4(ah[mf][0], ah[mf][1], ah[mf][2], ah[mf][3],
                     sb + aoff + mf * (16*SMS*2) + kst * 32);
                ldm4(al[mf][0], al[mf][1], al[mf][2], al[mf][3],
                     sb + TILE_B + aoff + mf * (16*SMS*2) + kst * 32);
            }
            #pragma unroll
            for (int p = 0; p < 2; p++) {
                ldm4(bh[2*p][0], bh[2*p][1], bh[2*p+1][0], bh[2*p+1][1],
                     sb + 2*TILE_B + boff + p * (16*SMS*2) + kst * 32);
                ldm4(bl[2*p][0], bl[2*p][1], bl[2*p+1][0], bl[2*p+1][1],
                     sb + 3*TILE_B + boff + p * (16*SMS*2) + kst * 32);
            }
            #pragma unroll
            for (int mf = 0; mf < 4; mf++)
                #pragma unroll
                for (int nf = 0; nf < 4; nf++) {
                    mma16816(acc[mf][nf], ah[mf], bh[nf]);
                    mma16816(acc[mf][nf], al[mf], bh[nf]);
                    mma16816(acc[mf][nf], ah[mf], bl[nf]);
                }
        }
        __syncthreads();
        if (i + 1 < nch) store_s((i + 1) & 1);
    }

    // -- epilogue from accumulator fragments
    const int qr = lane >> 2, qc = (lane & 3) * 2;
    #pragma unroll
    for (int mf = 0; mf < 4; mf++) {
        int row = m0 + wm + mf * 16 + qr;
        #pragma unroll
        for (int nf = 0; nf < 4; nf++) {
            int col = n0 + wn + nf * 8 + qc;
            float b0 = bias[col], b1 = bias[col + 1];
            float v0 = acc[mf][nf][0] + b0, v1 = acc[mf][nf][1] + b1;
            float v2 = acc[mf][nf][2] + b0, v3 = acc[mf][nf][3] + b1;
            if (EPI == 0) {
                *(float2*)(Cf + (size_t)row * N + col)       = make_float2(v0, v1);
                *(float2*)(Cf + (size_t)(row + 8) * N + col) = make_float2(v2, v3);
            } else if (EPI == 1) {
                v0 = 0.5f * v0 * (1.0f + erff(v0 * 0.70710678118654752f));
                v1 = 0.5f * v1 * (1.0f + erff(v1 * 0.70710678118654752f));
                v2 = 0.5f * v2 * (1.0f + erff(v2 * 0.70710678118654752f));
                v3 = 0.5f * v3 * (1.0f + erff(v3 * 0.70710678118654752f));
                size_t o0 = (size_t)row * N + col, o1 = (size_t)(row + 8) * N + col;
                split_store(Ch, Cl, o0,     v0); split_store(Ch, Cl, o0 + 1, v1);
                split_store(Ch, Cl, o1,     v2); split_store(Ch, Cl, o1 + 1, v3);
            } else {
                float2 r0v = *(const float2*)(res + (size_t)row * N + col);
                float2 r1v = *(const float2*)(res + (size_t)(row + 8) * N + col);
                *(float2*)(Cf + (size_t)row * N + col)       = make_float2(v0 + r0v.x, v1 + r0v.y);
                *(float2*)(Cf + (size_t)(row + 8) * N + col) = make_float2(v2 + r1v.x, v3 + r1v.y);
            }
        }
    }
}

// ---------------------------------------------------------------------------
// Weight transpose + bf16 hi/lo split: W[K][N] fp32 -> Wt_hi/lo[N][K]
// ---------------------------------------------------------------------------
__global__ __launch_bounds__(256)
void wsplit_kernel(const float* __restrict__ W, __nv_bfloat16* __restrict__ Hh,
                   __nv_bfloat16* __restrict__ Hl, int K, int N)
{
    int e = blockIdx.x * 256 + threadIdx.x;
    if (e >= K * N) return;
    int k = e / N, n = e - k * N;
    split_store(Hh, Hl, (size_t)n * K + k, W[e]);
}

// ---------------------------------------------------------------------------
// LayerNorm (+optional shift/window gather), outputs bf16 hi/lo
// ---------------------------------------------------------------------------
__global__ __launch_bounds__(128)
void ln_kernel(const float* __restrict__ x, const float* __restrict__ gam,
               const float* __restrict__ bet, __nv_bfloat16* __restrict__ oh,
               __nv_bfloat16* __restrict__ ol, int shifted)
{
    int tr = blockIdx.x;
    int src;
    if (shifted) {
        int bn = tr / NWIN_T;
        int n  = tr - bn * NWIN_T;
        int b  = bn / NWIN;
        int wi = bn - b * NWIN;
        int wy = wi / NWX, wx = wi - wy * NWX;
        int r  = n / WS,   cc = n - r * WS;
        int hs = (wy * WS + r  + SHIFT) % HIMG;
        int ws2= (wx * WS + cc + SHIFT) % WIMG;
        src = b * LTOK + hs * WIMG + ws2;
    } else src = tr;

    const float* xin = x + (size_t)src * CDIM;
    int tid = threadIdx.x;
    float v0 = xin[tid], v1 = xin[tid + 128], v2 = xin[tid + 256];
    float s  = v0 + v1 + v2;
    float ss = v0*v0 + v1*v1 + v2*v2;
    #pragma unroll
    for (int o = 16; o > 0; o >>= 1) {
        s  += __shfl_down_sync(0xffffffffu, s,  o);
        ss += __shfl_down_sync(0xffffffffu, ss, o);
    }
    __shared__ float red[8];
    __shared__ float mbv[2];
    int w = tid >> 5, l = tid & 31;
    if (l == 0) { red[w] = s; red[4 + w] = ss; }
    __syncthreads();
    if (tid == 0) {
        float S  = red[0] + red[1] + red[2] + red[3];
        float SS = red[4] + red[5] + red[6] + red[7];
        float mean = S * (1.0f / CDIM);
        float var  = SS * (1.0f / CDIM) - mean * mean;
        mbv[0] = mean; mbv[1] = rsqrtf(var + 1e-5f);
    }
    __syncthreads();
    float mean = mbv[0], rstd = mbv[1];
    size_t ob = (size_t)tr * CDIM;
    split_store(oh, ol, ob + tid,       (v0 - mean) * rstd * gam[tid]       + bet[tid]);
    split_store(oh, ol, ob + tid + 128, (v1 - mean) * rstd * gam[tid + 128] + bet[tid + 128]);
    split_store(oh, ol, ob + tid + 256, (v2 - mean) * rstd * gam[tid + 256] + bet[tid + 256]);
}

// ---------------------------------------------------------------------------
// Windowed attention: one block per (window, head). Writes bf16 hi/lo.
// ---------------------------------------------------------------------------
__global__ __launch_bounds__(128)
void attn_kernel(const float* __restrict__ qkv, const float* __restrict__ mask,
                 const float* __restrict__ rpb, __nv_bfloat16* __restrict__ oh,
                 __nv_bfloat16* __restrict__ ol)
{
    __shared__ float Qs[NWIN_T * 32];
    __shared__ float Ks[NWIN_T * 33];
    __shared__ float Vs[NWIN_T * 32];
    __shared__ float Ss[NWIN_T * NWIN_T];

    int bn = blockIdx.x, h = blockIdx.y, tid = threadIdx.x;
    const float scale = 0.1767766952966369f;

    size_t basep = (size_t)bn * NWIN_T * (3 * CDIM) + h * HD;
    for (int idx = tid; idx < NWIN_T * 32; idx += 128) {
        int n = idx >> 5, d = idx & 31;
        size_t p = basep + (size_t)n * (3 * CDIM) + d;
        Qs[idx]        = qkv[p] * scale;
        Ks[n * 33 + d] = qkv[p + CDIM];
        Vs[idx]        = qkv[p + 2 * CDIM];
    }
    __syncthreads();

    const float* mw = mask + (bn & (NWIN - 1)) * (NWIN_T * NWIN_T);
    for (int pix = tid; pix < NWIN_T * NWIN_T; pix += 128) {
        int n = pix / NWIN_T, m = pix - n * NWIN_T;
        float acc = 0.0f;
        #pragma unroll
        for (int d = 0; d < 32; d++) acc += Qs[n * 32 + d] * Ks[m * 33 + d];
        int r1 = n / WS, c1 = n - r1 * WS;
        int r2 = m / WS, c2 = m - r2 * WS;
        int rel = (r1 - r2 + WS - 1) * (2 * WS - 1) + (c1 - c2 + WS - 1);
        Ss[pix] = acc + rpb[rel * NHEADS + h] + mw[pix];
    }
    __syncthreads();

    if (tid < NWIN_T) {
        float* row = Ss + tid * NWIN_T;
        float mx = -1e30f;
        #pragma unroll 7
        for (int m = 0; m < NWIN_T; m++) mx = fmaxf(mx, row[m]);
        float sum = 0.0f;
        #pragma unroll 7
        for (int m = 0; m < NWIN_T; m++) { float e = __expf(row[m] - mx); row[m] = e; sum += e; }
        float inv = 1.0f / sum;
        #pragma unroll 7
        for (int m = 0; m < NWIN_T; m++) row[m] *= inv;
    }
    __syncthreads();

    for (int idx = tid; idx < NWIN_T * 32; idx += 128) {
        int n = idx >> 5, d = idx & 31;
        float acc = 0.0f;
        #pragma unroll 7
        for (int m = 0; m < NWIN_T; m++) acc += Ss[n * NWIN_T + m] * Vs[m * 32 + d];
        split_store(oh, ol, (size_t)(bn * NWIN_T + n) * CDIM + h * HD + d, acc);
    }
}

// ---------------------------------------------------------------------------
// Window-reverse + roll + residual
// ---------------------------------------------------------------------------
__global__ __launch_bounds__(256)
void merge_kernel(const float* __restrict__ x, const float* __restrict__ proj,
                  float* __restrict__ y)
{
    size_t e = (size_t)blockIdx.x * blockDim.x + threadIdx.x;
    const size_t TOT = (size_t)MTOK * CDIM;
    if (e >= TOT) return;
    int row = (int)(e / CDIM), c = (int)(e - (size_t)row * CDIM);
    int b = row / LTOK, pos = row - b * LTOK;
    int i = pos / WIMG, j = pos - i * WIMG;
    int ii = (i + HIMG - SHIFT) % HIMG;
    int jj = (j + WIMG - SHIFT) % WIMG;
    int tr = (b * NWIN + (ii / WS) * NWX + (jj / WS)) * NWIN_T + (ii % WS) * WS + (jj % WS);
    y[e] = x[e] + proj[(size_t)tr * CDIM + c];
}

// ---------------------------------------------------------------------------
// Launch
// ---------------------------------------------------------------------------
extern "C" void kernel_launch(void* const* d_in, const int* in_sizes, int n_in,
                              void* d_out, int out_size)
{
    const float* x        = (const float*)d_in[0];
    const float* attnmask = (const float*)d_in[1];
    const float* norm1_g  = (const float*)d_in[2];
    const float* norm1_b  = (const float*)d_in[3];
    const float* qkv_w    = (const float*)d_in[4];
    const float* qkv_b    = (const float*)d_in[5];
    const float* rpb      = (const float*)d_in[6];
    const float* proj_w   = (const float*)d_in[7];
    const float* proj_b   = (const float*)d_in[8];
    const float* norm2_g  = (const float*)d_in[9];
    const float* norm2_b  = (const float*)d_in[10];
    const float* fc1_w    = (const float*)d_in[11];
    const float* fc1_b    = (const float*)d_in[12];
    const float* fc2_w    = (const float*)d_in[13];
    const float* fc2_b    = (const float*)d_in[14];
    (void)in_sizes; (void)n_in; (void)out_size;

    float *qkvbuf, *projb, *y;
    __nv_bfloat16 *winh, *winl, *atth, *attl, *h2h, *h2l, *mlph, *mlpl;
    __nv_bfloat16 *wqh, *wql, *wph, *wpl, *w1h, *w1l, *w2h, *w2l;
    cudaGetSymbolAddress((void**)&qkvbuf, g_qkv);
    cudaGetSymbolAddress((void**)&projb,  g_proj);
    cudaGetSymbolAddress((void**)&y,      g_y);
    cudaGetSymbolAddress((void**)&winh,   g_win_h); cudaGetSymbolAddress((void**)&winl, g_win_l);
    cudaGetSymbolAddress((void**)&atth,   g_att_h); cudaGetSymbolAddress((void**)&attl, g_att_l);
    cudaGetSymbolAddress((void**)&h2h,    g_h2_h);  cudaGetSymbolAddress((void**)&h2l,  g_h2_l);
    cudaGetSymbolAddress((void**)&mlph,   g_mlp_h); cudaGetSymbolAddress((void**)&mlpl, g_mlp_l);
    cudaGetSymbolAddress((void**)&wqh,    g_wq_h);  cudaGetSymbolAddress((void**)&wql,  g_wq_l);
    cudaGetSymbolAddress((void**)&wph,    g_wp_h);  cudaGetSymbolAddress((void**)&wpl,  g_wp_l);
    cudaGetSymbolAddress((void**)&w1h,    g_w1_h);  cudaGetSymbolAddress((void**)&w1l,  g_w1_l);
    cudaGetSymbolAddress((void**)&w2h,    g_w2_h);  cudaGetSymbolAddress((void**)&w2l,  g_w2_l);

    cudaFuncSetAttribute(mma_gemm<0>, cudaFuncAttributeMaxDynamicSharedMemorySize, GEMM_SMEM);
    cudaFuncSetAttribute(mma_gemm<1>, cudaFuncAttributeMaxDynamicSharedMemorySize, GEMM_SMEM);
    cudaFuncSetAttribute(mma_gemm<2>, cudaFuncAttributeMaxDynamicSharedMemorySize, GEMM_SMEM);

    // 0. weight transpose + split
    wsplit_kernel<<<(CDIM*3*CDIM + 255)/256, 256>>>(qkv_w,  wqh, wql, CDIM, 3*CDIM);
    wsplit_kernel<<<(CDIM*CDIM   + 255)/256, 256>>>(proj_w, wph, wpl, CDIM, CDIM);
    wsplit_kernel<<<(CDIM*HID    + 255)/256, 256>>>(fc1_w,  w1h, w1l, CDIM, HID);
    wsplit_kernel<<<(HID*CDIM    + 255)/256, 256>>>(fc2_w,  w2h, w2l, HID,  CDIM);

    // 1. LN1 + shift + window partition (bf16 hi/lo)
    ln_kernel<<<MTOK, 128>>>(x, norm1_g, norm1_b, winh, winl, 1);

    // 2. QKV GEMM (100352 x 384) @ (384 x 1152)
    mma_gemm<0><<<dim3(9, MTOK/128), 256, GEMM_SMEM>>>(
        winh, winl, wqh, wql, qkv_b, nullptr, qkvbuf, nullptr, nullptr, 3*CDIM, CDIM);

    // 3. Windowed attention
    attn_kernel<<<dim3(BN, NHEADS), 128>>>(qkvbuf, attnmask, rpb, atth, attl);

    // 4. proj GEMM
    mma_gemm<0><<<dim3(3, MTOK/128), 256, GEMM_SMEM>>>(
        atth, attl, wph, wpl, proj_b, nullptr, projb, nullptr, nullptr, CDIM, CDIM);

    // 5. reverse + roll + residual
    merge_kernel<<<((size_t)MTOK*CDIM + 255)/256, 256>>>(x, projb, y);

    // 6. LN2 (bf16 hi/lo)
    ln_kernel<<<MTOK, 128>>>(y, norm2_g, norm2_b, h2h, h2l, 0);

    // 7. fc1 + GELU (bf16 hi/lo out)
    mma_gemm<1><<<dim3(12, MTOK/128), 256, GEMM_SMEM>>>(
        h2h, h2l, w1h, w1l, fc1_b, nullptr, nullptr, mlph, mlpl, HID, CDIM);

    // 8. fc2 + residual -> d_out
    mma_gemm<2><<<dim3(3, MTOK/128), 256, GEMM_SMEM>>>(
        mlph, mlpl, w2h, w2l, fc2_b, y, (float*)d_out, nullptr, nullptr, CDIM, HID);
}

// round 6
// speedup vs baseline: 1.8792x; 1.1065x over previous
#include <cuda_runtime.h>
#include <cuda_bf16.h>
#include <math.h>
#include <stdint.h>

// ---------------------------------------------------------------------------
// Problem constants
// ---------------------------------------------------------------------------
#define BATCH   32
#define HIMG    56
#define WIMG    56
#define CDIM    384
#define LTOK    (HIMG*WIMG)          // 3136
#define NHEADS  12
#define HD      32
#define WS      7
#define NWIN_T  49
#define SHIFT   3
#define NWX     8
#define NWIN    64
#define BN      (BATCH*NWIN)         // 2048 windows
#define MTOK    (BN*NWIN_T)          // 100352 tokens
#define HID     1536

// ---------------------------------------------------------------------------
// Scratch (device globals)
// ---------------------------------------------------------------------------
__device__ float          g_qkv [(size_t)MTOK * 3 * CDIM];
__device__ float          g_proj[(size_t)MTOK * CDIM];
__device__ float          g_y   [(size_t)MTOK * CDIM];
__device__ __nv_bfloat16  g_win_h[(size_t)MTOK * CDIM];
__device__ __nv_bfloat16  g_win_l[(size_t)MTOK * CDIM];
__device__ __nv_bfloat16  g_att_h[(size_t)MTOK * CDIM];
__device__ __nv_bfloat16  g_att_l[(size_t)MTOK * CDIM];
__device__ __nv_bfloat16  g_h2_h [(size_t)MTOK * CDIM];
__device__ __nv_bfloat16  g_h2_l [(size_t)MTOK * CDIM];
__device__ __nv_bfloat16  g_mlp_h[(size_t)MTOK * HID];
__device__ __nv_bfloat16  g_mlp_l[(size_t)MTOK * HID];
// transposed + split weights: Wt[N][K]
__device__ __nv_bfloat16  g_wq_h[3*CDIM*CDIM], g_wq_l[3*CDIM*CDIM];
__device__ __nv_bfloat16  g_wp_h[CDIM*CDIM],   g_wp_l[CDIM*CDIM];
__device__ __nv_bfloat16  g_w1_h[HID*CDIM],    g_w1_l[HID*CDIM];
__device__ __nv_bfloat16  g_w2_h[CDIM*HID],    g_w2_l[CDIM*HID];

// ---------------------------------------------------------------------------
// Helpers
// ---------------------------------------------------------------------------
static __device__ __forceinline__ uint32_t s2u(const void* p) {
    return (uint32_t)__cvta_generic_to_shared(p);
}
static __device__ __forceinline__ void split_store(__nv_bfloat16* ph, __nv_bfloat16* pl,
                                                   size_t idx, float v) {
    __nv_bfloat16 h = __float2bfloat16(v);
    ph[idx] = h;
    pl[idx] = __float2bfloat16(v - __bfloat162float(h));
}
// vectorized pair store
static __device__ __forceinline__ void split_store2(__nv_bfloat16* ph, __nv_bfloat16* pl,
                                                    size_t idx, float v0, float v1) {
    __nv_bfloat16 h0 = __float2bfloat16(v0), h1 = __float2bfloat16(v1);
    __nv_bfloat162 hv; hv.x = h0; hv.y = h1;
    __nv_bfloat162 lv;
    lv.x = __float2bfloat16(v0 - __bfloat162float(h0));
    lv.y = __float2bfloat16(v1 - __bfloat162float(h1));
    *(__nv_bfloat162*)(ph + idx) = hv;
    *(__nv_bfloat162*)(pl + idx) = lv;
}
static __device__ __forceinline__ void ldm4(uint32_t& d0, uint32_t& d1, uint32_t& d2,
                                            uint32_t& d3, uint32_t a) {
    asm volatile("ldmatrix.sync.aligned.m8n8.x4.shared.b16 {%0,%1,%2,%3},[%4];"
                 : "=r"(d0), "=r"(d1), "=r"(d2), "=r"(d3) : "r"(a));
}
static __device__ __forceinline__ void mma16816(float* c, const uint32_t* a, const uint32_t* b) {
    asm volatile("mma.sync.aligned.m16n8k16.row.col.f32.bf16.bf16.f32 "
                 "{%0,%1,%2,%3},{%4,%5,%6,%7},{%8,%9},{%0,%1,%2,%3};"
                 : "+f"(c[0]), "+f"(c[1]), "+f"(c[2]), "+f"(c[3])
                 : "r"(a[0]), "r"(a[1]), "r"(a[2]), "r"(a[3]), "r"(b[0]), "r"(b[1]));
}
static __device__ __forceinline__ void cpa16(uint32_t dst, const void* src) {
    asm volatile("cp.async.cg.shared.global [%0], [%1], 16;"
                 :: "r"(dst), "l"(src) : "memory");
}

// ---------------------------------------------------------------------------
// HMMA GEMM: C[M,N] = (Ah+Al)[M,K] @ (Bh+Bl)[N,K]^T  (bf16x3 compensated)
// 128x128 block tile, BK=32, 8 warps (2x4), warp tile 64x32,
// 3-stage cp.async pipeline.
// EPI 0: fp32 out + bias | 1: bias+GELU -> bf16 hi/lo | 2: bias+residual -> fp32
// ---------------------------------------------------------------------------
#define SMS      40                       // smem row stride (bf16 elems)
#define TILE_B   (128*SMS*2)              // 10240 bytes per tile
#define STAGE_B  (4*TILE_B)               // Ah,Al,Bh,Bl : 40960 bytes
#define NSTAGE   3
#define GEMM_SMEM (NSTAGE*STAGE_B)        // 122880 bytes

template <int EPI>
__global__ __launch_bounds__(256)
void mma_gemm(const __nv_bfloat16* __restrict__ Ah, const __nv_bfloat16* __restrict__ Al,
              const __nv_bfloat16* __restrict__ Bh, const __nv_bfloat16* __restrict__ Bl,
              const float* __restrict__ bias, const float* __restrict__ res,
              float* __restrict__ Cf, __nv_bfloat16* __restrict__ Ch,
              __nv_bfloat16* __restrict__ Cl, int N, int K)
{
    extern __shared__ char sm[];
    const int tid  = threadIdx.x, lane = tid & 31, warp = tid >> 5;
    const int m0 = blockIdx.y * 128, n0 = blockIdx.x * 128;
    const int wm = (warp >> 2) * 64, wn = (warp & 3) * 32;

    // global source: each thread owns rows r0 and r0+64, cols c0..c0+7 of each tile
    const int r0 = tid >> 2, c0 = (tid & 3) * 8;
    const __nv_bfloat16* pAh = Ah + (size_t)(m0 + r0) * K + c0;
    const __nv_bfloat16* pAl = Al + (size_t)(m0 + r0) * K + c0;
    const __nv_bfloat16* pBh = Bh + (size_t)(n0 + r0) * K + c0;
    const __nv_bfloat16* pBl = Bl + (size_t)(n0 + r0) * K + c0;
    const size_t rstep = (size_t)64 * K;
    const uint32_t so0 = (uint32_t)(r0 * SMS + c0) * 2;
    const uint32_t so1 = (uint32_t)((r0 + 64) * SMS + c0) * 2;
    const uint32_t smb = s2u(sm);

    const int nch = K >> 5;

    auto issue_stage = [&](int i, int s) {
        int k0 = i << 5;
        uint32_t b = smb + (uint32_t)s * STAGE_B;
        cpa16(b + so0,              pAh + k0);
        cpa16(b + so1,              pAh + rstep + k0);
        cpa16(b + TILE_B + so0,     pAl + k0);
        cpa16(b + TILE_B + so1,     pAl + rstep + k0);
        cpa16(b + 2*TILE_B + so0,   pBh + k0);
        cpa16(b + 2*TILE_B + so1,   pBh + rstep + k0);
        cpa16(b + 3*TILE_B + so0,   pBl + k0);
        cpa16(b + 3*TILE_B + so1,   pBl + rstep + k0);
        asm volatile("cp.async.commit_group;" ::: "memory");
    };

    float acc[4][4][4];
    #pragma unroll
    for (int i = 0; i < 4; i++)
        #pragma unroll
        for (int j = 0; j < 4; j++)
            #pragma unroll
            for (int k = 0; k < 4; k++) acc[i][j][k] = 0.0f;

    // ldmatrix lane addressing
    const int tsel = lane >> 3, rlo = lane & 7;
    const uint32_t aoff = (uint32_t)((wm + rlo + (tsel & 1) * 8) * SMS + (tsel >> 1) * 8) * 2;
    const uint32_t boff = (uint32_t)((wn + rlo + (tsel >> 1) * 8) * SMS + (tsel & 1) * 8) * 2;

    issue_stage(0, 0);
    if (nch > 1) issue_stage(1, 1);

    int stage = 0;
    for (int i = 0; i < nch; i++) {
        int rem = nch - 1 - i;
        if (rem >= 1) asm volatile("cp.async.wait_group 1;" ::: "memory");
        else          asm volatile("cp.async.wait_group 0;" ::: "memory");
        __syncthreads();

        if (i + 2 < nch) {
            int s = stage + 2; if (s >= NSTAGE) s -= NSTAGE;
            issue_stage(i + 2, s);
        }

        const uint32_t sb = smb + (uint32_t)stage * STAGE_B;
        #pragma unroll
        for (int kst = 0; kst < 2; kst++) {
            uint32_t ah[4][4], al[4][4], bh[4][2], bl[4][2];
            #pragma unroll
            for (int mf = 0; mf < 4; mf++) {
                ldm4(ah[mf][0], ah[mf][1], ah[mf][2], ah[mf][3],
                     sb + aoff + mf * (16*SMS*2) + kst * 32);
                ldm4(al[mf][0], al[mf][1], al[mf][2], al[mf][3],
                     sb + TILE_B + aoff + mf * (16*SMS*2) + kst * 32);
            }
            #pragma unroll
            for (int p = 0; p < 2; p++) {
                ldm4(bh[2*p][0], bh[2*p][1], bh[2*p+1][0], bh[2*p+1][1],
                     sb + 2*TILE_B + boff + p * (16*SMS*2) + kst * 32);
                ldm4(bl[2*p][0], bl[2*p][1], bl[2*p+1][0], bl[2*p+1][1],
                     sb + 3*TILE_B + boff + p * (16*SMS*2) + kst * 32);
            }
            #pragma unroll
            for (int mf = 0; mf < 4; mf++)
                #pragma unroll
                for (int nf = 0; nf < 4; nf++) {
                    mma16816(acc[mf][nf], ah[mf], bh[nf]);
                    mma16816(acc[mf][nf], al[mf], bh[nf]);
                    mma16816(acc[mf][nf], ah[mf], bl[nf]);
                }
        }
        stage++; if (stage >= NSTAGE) stage = 0;
        __syncthreads();
    }

    // -- epilogue from accumulator fragments
    const int qr = lane >> 2, qc = (lane & 3) * 2;
    #pragma unroll
    for (int mf = 0; mf < 4; mf++) {
        int row = m0 + wm + mf * 16 + qr;
        #pragma unroll
        for (int nf = 0; nf < 4; nf++) {
            int col = n0 + wn + nf * 8 + qc;
            float b0 = bias[col], b1 = bias[col + 1];
            float v0 = acc[mf][nf][0] + b0, v1 = acc[mf][nf][1] + b1;
            float v2 = acc[mf][nf][2] + b0, v3 = acc[mf][nf][3] + b1;
            if (EPI == 0) {
                *(float2*)(Cf + (size_t)row * N + col)       = make_float2(v0, v1);
                *(float2*)(Cf + (size_t)(row + 8) * N + col) = make_float2(v2, v3);
            } else if (EPI == 1) {
                v0 = 0.5f * v0 * (1.0f + erff(v0 * 0.70710678118654752f));
                v1 = 0.5f * v1 * (1.0f + erff(v1 * 0.70710678118654752f));
                v2 = 0.5f * v2 * (1.0f + erff(v2 * 0.70710678118654752f));
                v3 = 0.5f * v3 * (1.0f + erff(v3 * 0.70710678118654752f));
                split_store2(Ch, Cl, (size_t)row * N + col,       v0, v1);
                split_store2(Ch, Cl, (size_t)(row + 8) * N + col, v2, v3);
            } else {
                float2 r0v = *(const float2*)(res + (size_t)row * N + col);
                float2 r1v = *(const float2*)(res + (size_t)(row + 8) * N + col);
                *(float2*)(Cf + (size_t)row * N + col)       = make_float2(v0 + r0v.x, v1 + r0v.y);
                *(float2*)(Cf + (size_t)(row + 8) * N + col) = make_float2(v2 + r1v.x, v3 + r1v.y);
            }
        }
    }
}

// ---------------------------------------------------------------------------
// Weight transpose + bf16 hi/lo split: W[K][N] fp32 -> Wt_hi/lo[N][K]
// ---------------------------------------------------------------------------
__global__ __launch_bounds__(256)
void wsplit_kernel(const float* __restrict__ W, __nv_bfloat16* __restrict__ Hh,
                   __nv_bfloat16* __restrict__ Hl, int K, int N)
{
    int e = blockIdx.x * 256 + threadIdx.x;
    if (e >= K * N) return;
    int k = e / N, n = e - k * N;
    split_store(Hh, Hl, (size_t)n * K + k, W[e]);
}

// ---------------------------------------------------------------------------
// LN1 + shift + window-partition gather, outputs bf16 hi/lo
// ---------------------------------------------------------------------------
__global__ __launch_bounds__(128)
void ln1_kernel(const float* __restrict__ x, const float* __restrict__ gam,
                const float* __restrict__ bet, __nv_bfloat16* __restrict__ oh,
                __nv_bfloat16* __restrict__ ol)
{
    int tr = blockIdx.x;
    int bn = tr / NWIN_T;
    int n  = tr - bn * NWIN_T;
    int b  = bn / NWIN;
    int wi = bn - b * NWIN;
    int wy = wi / NWX, wx = wi - wy * NWX;
    int r  = n / WS,   cc = n - r * WS;
    int hs = (wy * WS + r  + SHIFT) % HIMG;
    int ws2= (wx * WS + cc + SHIFT) % WIMG;
    int src = b * LTOK + hs * WIMG + ws2;

    const float* xin = x + (size_t)src * CDIM;
    int tid = threadIdx.x;
    float v0 = xin[tid], v1 = xin[tid + 128], v2 = xin[tid + 256];
    float s  = v0 + v1 + v2;
    float ss = v0*v0 + v1*v1 + v2*v2;
    #pragma unroll
    for (int o = 16; o > 0; o >>= 1) {
        s  += __shfl_down_sync(0xffffffffu, s,  o);
        ss += __shfl_down_sync(0xffffffffu, ss, o);
    }
    __shared__ float red[8];
    __shared__ float mbv[2];
    int w = tid >> 5, l = tid & 31;
    if (l == 0) { red[w] = s; red[4 + w] = ss; }
    __syncthreads();
    if (tid == 0) {
        float S  = red[0] + red[1] + red[2] + red[3];
        float SS = red[4] + red[5] + red[6] + red[7];
        float mean = S * (1.0f / CDIM);
        float var  = SS * (1.0f / CDIM) - mean * mean;
        mbv[0] = mean; mbv[1] = rsqrtf(var + 1e-5f);
    }
    __syncthreads();
    float mean = mbv[0], rstd = mbv[1];
    size_t ob = (size_t)tr * CDIM;
    split_store(oh, ol, ob + tid,       (v0 - mean) * rstd * gam[tid]       + bet[tid]);
    split_store(oh, ol, ob + tid + 128, (v1 - mean) * rstd * gam[tid + 128] + bet[tid + 128]);
    split_store(oh, ol, ob + tid + 256, (v2 - mean) * rstd * gam[tid + 256] + bet[tid + 256]);
}

// ---------------------------------------------------------------------------
// Fused: window-reverse + roll + residual (y = x + unshuffle(proj)), then LN2
// One block per output token. Writes y (fp32) and h2 (bf16 hi/lo).
// ---------------------------------------------------------------------------
__global__ __launch_bounds__(128)
void mergeln_kernel(const float* __restrict__ x, const float* __restrict__ proj,
                    const float* __restrict__ gam, const float* __restrict__ bet,
                    float* __restrict__ y, __nv_bfloat16* __restrict__ oh,
                    __nv_bfloat16* __restrict__ ol)
{
    int tr = blockIdx.x;
    int b = tr / LTOK, pos = tr - b * LTOK;
    int i = pos / WIMG, j = pos - i * WIMG;
    int ii = (i + HIMG - SHIFT) % HIMG;
    int jj = (j + WIMG - SHIFT) % WIMG;
    int wr = (b * NWIN + (ii / WS) * NWX + (jj / WS)) * NWIN_T + (ii % WS) * WS + (jj % WS);

    const float* xp = x    + (size_t)tr * CDIM;
    const float* pp = proj + (size_t)wr * CDIM;
    int tid = threadIdx.x;
    float v0 = xp[tid]       + pp[tid];
    float v1 = xp[tid + 128] + pp[tid + 128];
    float v2 = xp[tid + 256] + pp[tid + 256];

    float* yp = y + (size_t)tr * CDIM;
    yp[tid] = v0; yp[tid + 128] = v1; yp[tid + 256] = v2;

    float s  = v0 + v1 + v2;
    float ss = v0*v0 + v1*v1 + v2*v2;
    #pragma unroll
    for (int o = 16; o > 0; o >>= 1) {
        s  += __shfl_down_sync(0xffffffffu, s,  o);
        ss += __shfl_down_sync(0xffffffffu, ss, o);
    }
    __shared__ float red[8];
    __shared__ float mbv[2];
    int w = tid >> 5, l = tid & 31;
    if (l == 0) { red[w] = s; red[4 + w] = ss; }
    __syncthreads();
    if (tid == 0) {
        float S  = red[0] + red[1] + red[2] + red[3];
        float SS = red[4] + red[5] + red[6] + red[7];
        float mean = S * (1.0f / CDIM);
        float var  = SS * (1.0f / CDIM) - mean * mean;
        mbv[0] = mean; mbv[1] = rsqrtf(var + 1e-5f);
    }
    __syncthreads();
    float mean = mbv[0], rstd = mbv[1];
    size_t ob = (size_t)tr * CDIM;
    split_store(oh, ol, ob + tid,       (v0 - mean) * rstd * gam[tid]       + bet[tid]);
    split_store(oh, ol, ob + tid + 128, (v1 - mean) * rstd * gam[tid + 128] + bet[tid + 128]);
    split_store(oh, ol, ob + tid + 256, (v2 - mean) * rstd * gam[tid + 256] + bet[tid + 256]);
}

// ---------------------------------------------------------------------------
// Windowed attention: one block per (window, head). Writes bf16 hi/lo.
// ---------------------------------------------------------------------------
__global__ __launch_bounds__(128)
void attn_kernel(const float* __restrict__ qkv, const float* __restrict__ mask,
                 const float* __restrict__ rpb, __nv_bfloat16* __restrict__ oh,
                 __nv_bfloat16* __restrict__ ol)
{
    __shared__ float Qs[NWIN_T * 32];
    __shared__ float Ks[NWIN_T * 33];
    __shared__ float Vs[NWIN_T * 32];
    __shared__ float Ss[NWIN_T * NWIN_T];

    int bn = blockIdx.x, h = blockIdx.y, tid = threadIdx.x;
    const float scale = 0.1767766952966369f;

    size_t basep = (size_t)bn * NWIN_T * (3 * CDIM) + h * HD;
    for (int idx = tid; idx < NWIN_T * 32; idx += 128) {
        int n = idx >> 5, d = idx & 31;
        size_t p = basep + (size_t)n * (3 * CDIM) + d;
        Qs[idx]        = qkv[p] * scale;
        Ks[n * 33 + d] = qkv[p + CDIM];
        Vs[idx]        = qkv[p + 2 * CDIM];
    }
    __syncthreads();

    const float* mw = mask + (bn & (NWIN - 1)) * (NWIN_T * NWIN_T);
    for (int pix = tid; pix < NWIN_T * NWIN_T; pix += 128) {
        int n = pix / NWIN_T, m = pix - n * NWIN_T;
        float acc = 0.0f;
        #pragma unroll
        for (int d = 0; d < 32; d++) acc += Qs[n * 32 + d] * Ks[m * 33 + d];
        int r1 = n / WS, c1 = n - r1 * WS;
        int r2 = m / WS, c2 = m - r2 * WS;
        int rel = (r1 - r2 + WS - 1) * (2 * WS - 1) + (c1 - c2 + WS - 1);
        Ss[pix] = acc + rpb[rel * NHEADS + h] + mw[pix];
    }
    __syncthreads();

    if (tid < NWIN_T) {
        float* row = Ss + tid * NWIN_T;
        float mx = -1e30f;
        #pragma unroll 7
        for (int m = 0; m < NWIN_T; m++) mx = fmaxf(mx, row[m]);
        float sum = 0.0f;
        #pragma unroll 7
        for (int m = 0; m < NWIN_T; m++) { float e = __expf(row[m] - mx); row[m] = e; sum += e; }
        float inv = 1.0f / sum;
        #pragma unroll 7
        for (int m = 0; m < NWIN_T; m++) row[m] *= inv;
    }
    __syncthreads();

    // PV: each thread owns a (row, channel-pair); vectorized bf162 stores
    for (int idx = tid; idx < NWIN_T * 16; idx += 128) {
        int n = idx >> 4, dp = idx & 15;
        int d = dp * 2;
        float a0 = 0.0f, a1 = 0.0f;
        #pragma unroll 7
        for (int m = 0; m < NWIN_T; m++) {
            float p = Ss[n * NWIN_T + m];
            a0 += p * Vs[m * 32 + d];
            a1 += p * Vs[m * 32 + d + 1];
        }
        split_store2(oh, ol, (size_t)(bn * NWIN_T + n) * CDIM + h * HD + d, a0, a1);
    }
}

// ---------------------------------------------------------------------------
// Launch
// ---------------------------------------------------------------------------
extern "C" void kernel_launch(void* const* d_in, const int* in_sizes, int n_in,
                              void* d_out, int out_size)
{
    const float* x        = (const float*)d_in[0];
    const float* attnmask = (const float*)d_in[1];
    const float* norm1_g  = (const float*)d_in[2];
    const float* norm1_b  = (const float*)d_in[3];
    const float* qkv_w    = (const float*)d_in[4];
    const float* qkv_b    = (const float*)d_in[5];
    const float* rpb      = (const float*)d_in[6];
    const float* proj_w   = (const float*)d_in[7];
    const float* proj_b   = (const float*)d_in[8];
    const float* norm2_g  = (const float*)d_in[9];
    const float* norm2_b  = (const float*)d_in[10];
    const float* fc1_w    = (const float*)d_in[11];
    const float* fc1_b    = (const float*)d_in[12];
    const float* fc2_w    = (const float*)d_in[13];
    const float* fc2_b    = (const float*)d_in[14];
    (void)in_sizes; (void)n_in; (void)out_size;

    float *qkvbuf, *projb, *y;
    __nv_bfloat16 *winh, *winl, *atth, *attl, *h2h, *h2l, *mlph, *mlpl;
    __nv_bfloat16 *wqh, *wql, *wph, *wpl, *w1h, *w1l, *w2h, *w2l;
    cudaGetSymbolAddress((void**)&qkvbuf, g_qkv);
    cudaGetSymbolAddress((void**)&projb,  g_proj);
    cudaGetSymbolAddress((void**)&y,      g_y);
    cudaGetSymbolAddress((void**)&winh,   g_win_h); cudaGetSymbolAddress((void**)&winl, g_win_l);
    cudaGetSymbolAddress((void**)&atth,   g_att_h); cudaGetSymbolAddress((void**)&attl, g_att_l);
    cudaGetSymbolAddress((void**)&h2h,    g_h2_h);  cudaGetSymbolAddress((void**)&h2l,  g_h2_l);
    cudaGetSymbolAddress((void**)&mlph,   g_mlp_h); cudaGetSymbolAddress((void**)&mlpl, g_mlp_l);
    cudaGetSymbolAddress((void**)&wqh,    g_wq_h);  cudaGetSymbolAddress((void**)&wql,  g_wq_l);
    cudaGetSymbolAddress((void**)&wph,    g_wp_h);  cudaGetSymbolAddress((void**)&wpl,  g_wp_l);
    cudaGetSymbolAddress((void**)&w1h,    g_w1_h);  cudaGetSymbolAddress((void**)&w1l,  g_w1_l);
    cudaGetSymbolAddress((void**)&w2h,    g_w2_h);  cudaGetSymbolAddress((void**)&w2l,  g_w2_l);

    cudaFuncSetAttribute(mma_gemm<0>, cudaFuncAttributeMaxDynamicSharedMemorySize, GEMM_SMEM);
    cudaFuncSetAttribute(mma_gemm<1>, cudaFuncAttributeMaxDynamicSharedMemorySize, GEMM_SMEM);
    cudaFuncSetAttribute(mma_gemm<2>, cudaFuncAttributeMaxDynamicSharedMemorySize, GEMM_SMEM);

    // 0. weight transpose + split
    wsplit_kernel<<<(CDIM*3*CDIM + 255)/256, 256>>>(qkv_w,  wqh, wql, CDIM, 3*CDIM);
    wsplit_kernel<<<(CDIM*CDIM   + 255)/256, 256>>>(proj_w, wph, wpl, CDIM, CDIM);
    wsplit_kernel<<<(CDIM*HID    + 255)/256, 256>>>(fc1_w,  w1h, w1l, CDIM, HID);
    wsplit_kernel<<<(HID*CDIM    + 255)/256, 256>>>(fc2_w,  w2h, w2l, HID,  CDIM);

    // 1. LN1 + shift + window partition (bf16 hi/lo)
    ln1_kernel<<<MTOK, 128>>>(x, norm1_g, norm1_b, winh, winl);

    // 2. QKV GEMM (100352 x 384) @ (384 x 1152)
    mma_gemm<0><<<dim3(9, MTOK/128), 256, GEMM_SMEM>>>(
        winh, winl, wqh, wql, qkv_b, nullptr, qkvbuf, nullptr, nullptr, 3*CDIM, CDIM);

    // 3. Windowed attention
    attn_kernel<<<dim3(BN, NHEADS), 128>>>(qkvbuf, attnmask, rpb, atth, attl);

    // 4. proj GEMM
    mma_gemm<0><<<dim3(3, MTOK/128), 256, GEMM_SMEM>>>(
        atth, attl, wph, wpl, proj_b, nullptr, projb, nullptr, nullptr, CDIM, CDIM);

    // 5+6. reverse + roll + residual + LN2 (fused)
    mergeln_kernel<<<MTOK, 128>>>(x, projb, norm2_g, norm2_b, y, h2h, h2l);

    // 7. fc1 + GELU (bf16 hi/lo out)
    mma_gemm<1><<<dim3(12, MTOK/128), 256, GEMM_SMEM>>>(
        h2h, h2l, w1h, w1l, fc1_b, nullptr, nullptr, mlph, mlpl, HID, CDIM);

    // 8. fc2 + residual -> d_out
    mma_gemm<2><<<dim3(3, MTOK/128), 256, GEMM_SMEM>>>(
        mlph, mlpl, w2h, w2l, fc2_b, y, (float*)d_out, nullptr, nullptr, CDIM, HID);
}

// round 7
// speedup vs baseline: 2.2167x; 1.1796x over previous
#include <cuda_runtime.h>
#include <cuda_bf16.h>
#include <math.h>
#include <stdint.h>

// ---------------------------------------------------------------------------
// Problem constants
// ---------------------------------------------------------------------------
#define BATCH   32
#define HIMG    56
#define WIMG    56
#define CDIM    384
#define LTOK    (HIMG*WIMG)          // 3136
#define NHEADS  12
#define HD      32
#define WS      7
#define NWIN_T  49
#define SHIFT   3
#define NWX     8
#define NWIN    64
#define BN      (BATCH*NWIN)         // 2048 windows
#define MTOK    (BN*NWIN_T)          // 100352 tokens
#define HID     1536

// ---------------------------------------------------------------------------
// Scratch (device globals)
// ---------------------------------------------------------------------------
__device__ float          g_qkv [(size_t)MTOK * 3 * CDIM];
__device__ float          g_proj[(size_t)MTOK * CDIM];
__device__ float          g_y   [(size_t)MTOK * CDIM];
__device__ __nv_bfloat16  g_win_h[(size_t)MTOK * CDIM];
__device__ __nv_bfloat16  g_win_l[(size_t)MTOK * CDIM];
__device__ __nv_bfloat16  g_att_h[(size_t)MTOK * CDIM];
__device__ __nv_bfloat16  g_att_l[(size_t)MTOK * CDIM];
__device__ __nv_bfloat16  g_h2_h [(size_t)MTOK * CDIM];
__device__ __nv_bfloat16  g_h2_l [(size_t)MTOK * CDIM];
__device__ __nv_bfloat16  g_mlp_h[(size_t)MTOK * HID];
__device__ __nv_bfloat16  g_mlp_l[(size_t)MTOK * HID];
// transposed + split weights: Wt[N][K]
__device__ __nv_bfloat16  g_wq_h[3*CDIM*CDIM], g_wq_l[3*CDIM*CDIM];
__device__ __nv_bfloat16  g_wp_h[CDIM*CDIM],   g_wp_l[CDIM*CDIM];
__device__ __nv_bfloat16  g_w1_h[HID*CDIM],    g_w1_l[HID*CDIM];
__device__ __nv_bfloat16  g_w2_h[CDIM*HID],    g_w2_l[CDIM*HID];

// ---------------------------------------------------------------------------
// Helpers
// ---------------------------------------------------------------------------
static __device__ __forceinline__ uint32_t s2u(const void* p) {
    return (uint32_t)__cvta_generic_to_shared(p);
}
static __device__ __forceinline__ void split_store(__nv_bfloat16* ph, __nv_bfloat16* pl,
                                                   size_t idx, float v) {
    __nv_bfloat16 h = __float2bfloat16(v);
    ph[idx] = h;
    pl[idx] = __float2bfloat16(v - __bfloat162float(h));
}
static __device__ __forceinline__ void split_store2(__nv_bfloat16* ph, __nv_bfloat16* pl,
                                                    size_t idx, float v0, float v1) {
    __nv_bfloat16 h0 = __float2bfloat16(v0), h1 = __float2bfloat16(v1);
    __nv_bfloat162 hv; hv.x = h0; hv.y = h1;
    __nv_bfloat162 lv;
    lv.x = __float2bfloat16(v0 - __bfloat162float(h0));
    lv.y = __float2bfloat16(v1 - __bfloat162float(h1));
    *(__nv_bfloat162*)(ph + idx) = hv;
    *(__nv_bfloat162*)(pl + idx) = lv;
}
static __device__ __forceinline__ void ldm4(uint32_t& d0, uint32_t& d1, uint32_t& d2,
                                            uint32_t& d3, uint32_t a) {
    asm volatile("ldmatrix.sync.aligned.m8n8.x4.shared.b16 {%0,%1,%2,%3},[%4];"
                 : "=r"(d0), "=r"(d1), "=r"(d2), "=r"(d3) : "r"(a));
}
static __device__ __forceinline__ void mma16816(float* c, const uint32_t* a, const uint32_t* b) {
    asm volatile("mma.sync.aligned.m16n8k16.row.col.f32.bf16.bf16.f32 "
                 "{%0,%1,%2,%3},{%4,%5,%6,%7},{%8,%9},{%0,%1,%2,%3};"
                 : "+f"(c[0]), "+f"(c[1]), "+f"(c[2]), "+f"(c[3])
                 : "r"(a[0]), "r"(a[1]), "r"(a[2]), "r"(a[3]), "r"(b[0]), "r"(b[1]));
}
static __device__ __forceinline__ void cpa16(uint32_t dst, const void* src) {
    asm volatile("cp.async.cg.shared.global [%0], [%1], 16;"
                 :: "r"(dst), "l"(src) : "memory");
}

// ---------------------------------------------------------------------------
// HMMA GEMM: C[M,N] = (Ah+Al)[M,K] @ (Bh+Bl)[N,K]^T  (bf16x3 compensated)
// 128x128 block tile, BK=32, 8 warps (2x4), warp tile 64x32,
// 2-stage cp.async pipeline, 2 CTAs/SM.
// EPI 0: fp32 out + bias | 1: bias+GELU -> bf16 hi/lo | 2: bias+residual -> fp32
// ---------------------------------------------------------------------------
#define SMS      40                       // smem row stride (bf16 elems)
#define TILE_B   (128*SMS*2)              // 10240 bytes per tile
#define STAGE_B  (4*TILE_B)               // Ah,Al,Bh,Bl : 40960 bytes
#define NSTAGE   2
#define GEMM_SMEM (NSTAGE*STAGE_B)        // 81920 bytes

template <int EPI>
__global__ __launch_bounds__(256, 2)
void mma_gemm(const __nv_bfloat16* __restrict__ Ah, const __nv_bfloat16* __restrict__ Al,
              const __nv_bfloat16* __restrict__ Bh, const __nv_bfloat16* __restrict__ Bl,
              const float* __restrict__ bias, const float* __restrict__ res,
              float* __restrict__ Cf, __nv_bfloat16* __restrict__ Ch,
              __nv_bfloat16* __restrict__ Cl, int N, int K)
{
    extern __shared__ char sm[];
    const int tid  = threadIdx.x, lane = tid & 31, warp = tid >> 5;
    const int m0 = blockIdx.y * 128, n0 = blockIdx.x * 128;
    const int wm = (warp >> 2) * 64, wn = (warp & 3) * 32;

    // global source: each thread owns rows r0 and r0+64, cols c0..c0+7 of each tile
    const int r0 = tid >> 2, c0 = (tid & 3) * 8;
    const __nv_bfloat16* pAh = Ah + (size_t)(m0 + r0) * K + c0;
    const __nv_bfloat16* pAl = Al + (size_t)(m0 + r0) * K + c0;
    const __nv_bfloat16* pBh = Bh + (size_t)(n0 + r0) * K + c0;
    const __nv_bfloat16* pBl = Bl + (size_t)(n0 + r0) * K + c0;
    const size_t rstep = (size_t)64 * K;
    const uint32_t so0 = (uint32_t)(r0 * SMS + c0) * 2;
    const uint32_t so1 = (uint32_t)((r0 + 64) * SMS + c0) * 2;
    const uint32_t smb = s2u(sm);

    const int nch = K >> 5;

    auto issue_stage = [&](int i, int s) {
        int k0 = i << 5;
        uint32_t b = smb + (uint32_t)s * STAGE_B;
        cpa16(b + so0,              pAh + k0);
        cpa16(b + so1,              pAh + rstep + k0);
        cpa16(b + TILE_B + so0,     pAl + k0);
        cpa16(b + TILE_B + so1,     pAl + rstep + k0);
        cpa16(b + 2*TILE_B + so0,   pBh + k0);
        cpa16(b + 2*TILE_B + so1,   pBh + rstep + k0);
        cpa16(b + 3*TILE_B + so0,   pBl + k0);
        cpa16(b + 3*TILE_B + so1,   pBl + rstep + k0);
        asm volatile("cp.async.commit_group;" ::: "memory");
    };

    float acc[4][4][4];
    #pragma unroll
    for (int i = 0; i < 4; i++)
        #pragma unroll
        for (int j = 0; j < 4; j++)
            #pragma unroll
            for (int k = 0; k < 4; k++) acc[i][j][k] = 0.0f;

    // ldmatrix lane addressing
    const int tsel = lane >> 3, rlo = lane & 7;
    const uint32_t aoff = (uint32_t)((wm + rlo + (tsel & 1) * 8) * SMS + (tsel >> 1) * 8) * 2;
    const uint32_t boff = (uint32_t)((wn + rlo + (tsel >> 1) * 8) * SMS + (tsel & 1) * 8) * 2;

    issue_stage(0, 0);

    int stage = 0;
    for (int i = 0; i < nch; i++) {
        if (i + 1 < nch) {
            issue_stage(i + 1, stage ^ 1);
            asm volatile("cp.async.wait_group 1;" ::: "memory");
        } else {
            asm volatile("cp.async.wait_group 0;" ::: "memory");
        }
        __syncthreads();

        const uint32_t sb = smb + (uint32_t)stage * STAGE_B;
        #pragma unroll
        for (int kst = 0; kst < 2; kst++) {
            uint32_t bh[4][2], bl[4][2];
            #pragma unroll
            for (int p = 0; p < 2; p++) {
                ldm4(bh[2*p][0], bh[2*p][1], bh[2*p+1][0], bh[2*p+1][1],
                     sb + 2*TILE_B + boff + p * (16*SMS*2) + kst * 32);
                ldm4(bl[2*p][0], bl[2*p][1], bl[2*p+1][0], bl[2*p+1][1],
                     sb + 3*TILE_B + boff + p * (16*SMS*2) + kst * 32);
            }
            #pragma unroll
            for (int mf = 0; mf < 4; mf++) {
                uint32_t ah[4], al[4];
                ldm4(ah[0], ah[1], ah[2], ah[3],
                     sb + aoff + mf * (16*SMS*2) + kst * 32);
                ldm4(al[0], al[1], al[2], al[3],
                     sb + TILE_B + aoff + mf * (16*SMS*2) + kst * 32);
                #pragma unroll
                for (int nf = 0; nf < 4; nf++) {
                    mma16816(acc[mf][nf], ah, bh[nf]);
                    mma16816(acc[mf][nf], al, bh[nf]);
                    mma16816(acc[mf][nf], ah, bl[nf]);
                }
            }
        }
        stage ^= 1;
        __syncthreads();
    }

    // -- epilogue from accumulator fragments
    const int qr = lane >> 2, qc = (lane & 3) * 2;
    #pragma unroll
    for (int mf = 0; mf < 4; mf++) {
        int row = m0 + wm + mf * 16 + qr;
        #pragma unroll
        for (int nf = 0; nf < 4; nf++) {
            int col = n0 + wn + nf * 8 + qc;
            float b0 = bias[col], b1 = bias[col + 1];
            float v0 = acc[mf][nf][0] + b0, v1 = acc[mf][nf][1] + b1;
            float v2 = acc[mf][nf][2] + b0, v3 = acc[mf][nf][3] + b1;
            if (EPI == 0) {
                *(float2*)(Cf + (size_t)row * N + col)       = make_float2(v0, v1);
                *(float2*)(Cf + (size_t)(row + 8) * N + col) = make_float2(v2, v3);
            } else if (EPI == 1) {
                v0 = 0.5f * v0 * (1.0f + erff(v0 * 0.70710678118654752f));
                v1 = 0.5f * v1 * (1.0f + erff(v1 * 0.70710678118654752f));
                v2 = 0.5f * v2 * (1.0f + erff(v2 * 0.70710678118654752f));
                v3 = 0.5f * v3 * (1.0f + erff(v3 * 0.70710678118654752f));
                split_store2(Ch, Cl, (size_t)row * N + col,       v0, v1);
                split_store2(Ch, Cl, (size_t)(row + 8) * N + col, v2, v3);
            } else {
                float2 r0v = *(const float2*)(res + (size_t)row * N + col);
                float2 r1v = *(const float2*)(res + (size_t)(row + 8) * N + col);
                *(float2*)(Cf + (size_t)row * N + col)       = make_float2(v0 + r0v.x, v1 + r0v.y);
                *(float2*)(Cf + (size_t)(row + 8) * N + col) = make_float2(v2 + r1v.x, v3 + r1v.y);
            }
        }
    }
}

// ---------------------------------------------------------------------------
// Weight transpose + bf16 hi/lo split: W[K][N] fp32 -> Wt_hi/lo[N][K]
// ---------------------------------------------------------------------------
__global__ __launch_bounds__(256)
void wsplit_kernel(const float* __restrict__ W, __nv_bfloat16* __restrict__ Hh,
                   __nv_bfloat16* __restrict__ Hl, int K, int N)
{
    int e = blockIdx.x * 256 + threadIdx.x;
    if (e >= K * N) return;
    int k = e / N, n = e - k * N;
    split_store(Hh, Hl, (size_t)n * K + k, W[e]);
}

// ---------------------------------------------------------------------------
// LN1 + shift + window-partition gather, outputs bf16 hi/lo
// ---------------------------------------------------------------------------
__global__ __launch_bounds__(128)
void ln1_kernel(const float* __restrict__ x, const float* __restrict__ gam,
                const float* __restrict__ bet, __nv_bfloat16* __restrict__ oh,
                __nv_bfloat16* __restrict__ ol)
{
    int tr = blockIdx.x;
    int bn = tr / NWIN_T;
    int n  = tr - bn * NWIN_T;
    int b  = bn / NWIN;
    int wi = bn - b * NWIN;
    int wy = wi / NWX, wx = wi - wy * NWX;
    int r  = n / WS,   cc = n - r * WS;
    int hs = (wy * WS + r  + SHIFT) % HIMG;
    int ws2= (wx * WS + cc + SHIFT) % WIMG;
    int src = b * LTOK + hs * WIMG + ws2;

    const float* xin = x + (size_t)src * CDIM;
    int tid = threadIdx.x;
    float v0 = xin[tid], v1 = xin[tid + 128], v2 = xin[tid + 256];
    float s  = v0 + v1 + v2;
    float ss = v0*v0 + v1*v1 + v2*v2;
    #pragma unroll
    for (int o = 16; o > 0; o >>= 1) {
        s  += __shfl_down_sync(0xffffffffu, s,  o);
        ss += __shfl_down_sync(0xffffffffu, ss, o);
    }
    __shared__ float red[8];
    __shared__ float mbv[2];
    int w = tid >> 5, l = tid & 31;
    if (l == 0) { red[w] = s; red[4 + w] = ss; }
    __syncthreads();
    if (tid == 0) {
        float S  = red[0] + red[1] + red[2] + red[3];
        float SS = red[4] + red[5] + red[6] + red[7];
        float mean = S * (1.0f / CDIM);
        float var  = SS * (1.0f / CDIM) - mean * mean;
        mbv[0] = mean; mbv[1] = rsqrtf(var + 1e-5f);
    }
    __syncthreads();
    float mean = mbv[0], rstd = mbv[1];
    size_t ob = (size_t)tr * CDIM;
    split_store(oh, ol, ob + tid,       (v0 - mean) * rstd * gam[tid]       + bet[tid]);
    split_store(oh, ol, ob + tid + 128, (v1 - mean) * rstd * gam[tid + 128] + bet[tid + 128]);
    split_store(oh, ol, ob + tid + 256, (v2 - mean) * rstd * gam[tid + 256] + bet[tid + 256]);
}

// ---------------------------------------------------------------------------
// Fused: window-reverse + roll + residual, then LN2
// ---------------------------------------------------------------------------
__global__ __launch_bounds__(128)
void mergeln_kernel(const float* __restrict__ x, const float* __restrict__ proj,
                    const float* __restrict__ gam, const float* __restrict__ bet,
                    float* __restrict__ y, __nv_bfloat16* __restrict__ oh,
                    __nv_bfloat16* __restrict__ ol)
{
    int tr = blockIdx.x;
    int b = tr / LTOK, pos = tr - b * LTOK;
    int i = pos / WIMG, j = pos - i * WIMG;
    int ii = (i + HIMG - SHIFT) % HIMG;
    int jj = (j + WIMG - SHIFT) % WIMG;
    int wr = (b * NWIN + (ii / WS) * NWX + (jj / WS)) * NWIN_T + (ii % WS) * WS + (jj % WS);

    const float* xp = x    + (size_t)tr * CDIM;
    const float* pp = proj + (size_t)wr * CDIM;
    int tid = threadIdx.x;
    float v0 = xp[tid]       + pp[tid];
    float v1 = xp[tid + 128] + pp[tid + 128];
    float v2 = xp[tid + 256] + pp[tid + 256];

    float* yp = y + (size_t)tr * CDIM;
    yp[tid] = v0; yp[tid + 128] = v1; yp[tid + 256] = v2;

    float s  = v0 + v1 + v2;
    float ss = v0*v0 + v1*v1 + v2*v2;
    #pragma unroll
    for (int o = 16; o > 0; o >>= 1) {
        s  += __shfl_down_sync(0xffffffffu, s,  o);
        ss += __shfl_down_sync(0xffffffffu, ss, o);
    }
    __shared__ float red[8];
    __shared__ float mbv[2];
    int w = tid >> 5, l = tid & 31;
    if (l == 0) { red[w] = s; red[4 + w] = ss; }
    __syncthreads();
    if (tid == 0) {
        float S  = red[0] + red[1] + red[2] + red[3];
        float SS = red[4] + red[5] + red[6] + red[7];
        float mean = S * (1.0f / CDIM);
        float var  = SS * (1.0f / CDIM) - mean * mean;
        mbv[0] = mean; mbv[1] = rsqrtf(var + 1e-5f);
    }
    __syncthreads();
    float mean = mbv[0], rstd = mbv[1];
    size_t ob = (size_t)tr * CDIM;
    split_store(oh, ol, ob + tid,       (v0 - mean) * rstd * gam[tid]       + bet[tid]);
    split_store(oh, ol, ob + tid + 128, (v1 - mean) * rstd * gam[tid + 128] + bet[tid + 128]);
    split_store(oh, ol, ob + tid + 256, (v2 - mean) * rstd * gam[tid + 256] + bet[tid + 256]);
}

// ---------------------------------------------------------------------------
// Windowed attention: one block (64 thr) per (window, head).
// Thread n keeps Q row / output row in registers; K/V rows via broadcast LDS.128.
// ---------------------------------------------------------------------------
#define SST 50   // padded logits stride
__global__ __launch_bounds__(64)
void attn_kernel(const float* __restrict__ qkv, const float* __restrict__ mask,
                 const float* __restrict__ rpb, __nv_bfloat16* __restrict__ oh,
                 __nv_bfloat16* __restrict__ ol)
{
    __shared__ float Qs[NWIN_T * 32];
    __shared__ float Ks[NWIN_T * 32];
    __shared__ float Vs[NWIN_T * 32];
    __shared__ float Ss[NWIN_T * SST];

    int bn = blockIdx.x, h = blockIdx.y, tid = threadIdx.x;
    const float scale = 0.1767766952966369f;   // 32^-0.5

    size_t basep = (size_t)bn * NWIN_T * (3 * CDIM) + h * HD;
    for (int idx = tid; idx < NWIN_T * 8; idx += 64) {
        int n = idx >> 3, q = idx & 7;
        const float* rowp = qkv + basep + (size_t)n * (3 * CDIM);
        float4 qv = *(const float4*)(rowp + q * 4);
        qv.x *= scale; qv.y *= scale; qv.z *= scale; qv.w *= scale;
        *(float4*)&Qs[n * 32 + q * 4] = qv;
        *(float4*)&Ks[n * 32 + q * 4] = *(const float4*)(rowp + CDIM + q * 4);
        *(float4*)&Vs[n * 32 + q * 4] = *(const float4*)(rowp + 2 * CDIM + q * 4);
    }
    __syncthreads();

    if (tid < NWIN_T) {
        const int n = tid;
        const float* mw = mask + (bn & (NWIN - 1)) * (NWIN_T * NWIN_T) + n * NWIN_T;
        const int r1 = n / WS, c1 = n - r1 * WS;

        // Q row -> registers
        float q[32];
        #pragma unroll
        for (int i = 0; i < 8; i++) {
            float4 v = *(const float4*)&Qs[n * 32 + i * 4];
            q[i*4+0] = v.x; q[i*4+1] = v.y; q[i*4+2] = v.z; q[i*4+3] = v.w;
        }

        // logits
        for (int m = 0; m < NWIN_T; m++) {
            float acc = 0.0f;
            #pragma unroll
            for (int i = 0; i < 8; i++) {
                float4 kv = *(const float4*)&Ks[m * 32 + i * 4];
                acc += q[i*4+0]*kv.x + q[i*4+1]*kv.y + q[i*4+2]*kv.z + q[i*4+3]*kv.w;
            }
            int r2 = m / WS, c2 = m - r2 * WS;
            int rel = (r1 - r2 + WS - 1) * (2 * WS - 1) + (c1 - c2 + WS - 1);
            Ss[n * SST + m] = acc + rpb[rel * NHEADS + h] + mw[m];
        }

        // softmax (inv folded into output)
        float mx = -1e30f;
        for (int m = 0; m < NWIN_T; m++) mx = fmaxf(mx, Ss[n * SST + m]);
        float sum = 0.0f;
        for (int m = 0; m < NWIN_T; m++) {
            float e = __expf(Ss[n * SST + m] - mx);
            Ss[n * SST + m] = e; sum += e;
        }
        float inv = 1.0f / sum;

        // PV: output row in registers
        float acc[32];
        #pragma unroll
        for (int i = 0; i < 32; i++) acc[i] = 0.0f;
        for (int m = 0; m < NWIN_T; m++) {
            float p = Ss[n * SST + m];
            #pragma unroll
            for (int i = 0; i < 8; i++) {
                float4 vv = *(const float4*)&Vs[m * 32 + i * 4];
                acc[i*4+0] += p * vv.x; acc[i*4+1] += p * vv.y;
                acc[i*4+2] += p * vv.z; acc[i*4+3] += p * vv.w;
            }
        }
        size_t ob = (size_t)(bn * NWIN_T + n) * CDIM + h * HD;
        #pragma unroll
        for (int i = 0; i < 16; i++)
            split_store2(oh, ol, ob + 2*i, acc[2*i] * inv, acc[2*i+1] * inv);
    }
}

// ---------------------------------------------------------------------------
// Launch
// ---------------------------------------------------------------------------
extern "C" void kernel_launch(void* const* d_in, const int* in_sizes, int n_in,
                              void* d_out, int out_size)
{
    const float* x        = (const float*)d_in[0];
    const float* attnmask = (const float*)d_in[1];
    const float* norm1_g  = (const float*)d_in[2];
    const float* norm1_b  = (const float*)d_in[3];
    const float* qkv_w    = (const float*)d_in[4];
    const float* qkv_b    = (const float*)d_in[5];
    const float* rpb      = (const float*)d_in[6];
    const float* proj_w   = (const float*)d_in[7];
    const float* proj_b   = (const float*)d_in[8];
    const float* norm2_g  = (const float*)d_in[9];
    const float* norm2_b  = (const float*)d_in[10];
    const float* fc1_w    = (const float*)d_in[11];
    const float* fc1_b    = (const float*)d_in[12];
    const float* fc2_w    = (const float*)d_in[13];
    const float* fc2_b    = (const float*)d_in[14];
    (void)in_sizes; (void)n_in; (void)out_size;

    float *qkvbuf, *projb, *y;
    __nv_bfloat16 *winh, *winl, *atth, *attl, *h2h, *h2l, *mlph, *mlpl;
    __nv_bfloat16 *wqh, *wql, *wph, *wpl, *w1h, *w1l, *w2h, *w2l;
    cudaGetSymbolAddress((void**)&qkvbuf, g_qkv);
    cudaGetSymbolAddress((void**)&projb,  g_proj);
    cudaGetSymbolAddress((void**)&y,      g_y);
    cudaGetSymbolAddress((void**)&winh,   g_win_h); cudaGetSymbolAddress((void**)&winl, g_win_l);
    cudaGetSymbolAddress((void**)&atth,   g_att_h); cudaGetSymbolAddress((void**)&attl, g_att_l);
    cudaGetSymbolAddress((void**)&h2h,    g_h2_h);  cudaGetSymbolAddress((void**)&h2l,  g_h2_l);
    cudaGetSymbolAddress((void**)&mlph,   g_mlp_h); cudaGetSymbolAddress((void**)&mlpl, g_mlp_l);
    cudaGetSymbolAddress((void**)&wqh,    g_wq_h);  cudaGetSymbolAddress((void**)&wql,  g_wq_l);
    cudaGetSymbolAddress((void**)&wph,    g_wp_h);  cudaGetSymbolAddress((void**)&wpl,  g_wp_l);
    cudaGetSymbolAddress((void**)&w1h,    g_w1_h);  cudaGetSymbolAddress((void**)&w1l,  g_w1_l);
    cudaGetSymbolAddress((void**)&w2h,    g_w2_h);  cudaGetSymbolAddress((void**)&w2l,  g_w2_l);

    cudaFuncSetAttribute(mma_gemm<0>, cudaFuncAttributeMaxDynamicSharedMemorySize, GEMM_SMEM);
    cudaFuncSetAttribute(mma_gemm<1>, cudaFuncAttributeMaxDynamicSharedMemorySize, GEMM_SMEM);
    cudaFuncSetAttribute(mma_gemm<2>, cudaFuncAttributeMaxDynamicSharedMemorySize, GEMM_SMEM);

    // 0. weight transpose + split
    wsplit_kernel<<<(CDIM*3*CDIM + 255)/256, 256>>>(qkv_w,  wqh, wql, CDIM, 3*CDIM);
    wsplit_kernel<<<(CDIM*CDIM   + 255)/256, 256>>>(proj_w, wph, wpl, CDIM, CDIM);
    wsplit_kernel<<<(CDIM*HID    + 255)/256, 256>>>(fc1_w,  w1h, w1l, CDIM, HID);
    wsplit_kernel<<<(HID*CDIM    + 255)/256, 256>>>(fc2_w,  w2h, w2l, HID,  CDIM);

    // 1. LN1 + shift + window partition (bf16 hi/lo)
    ln1_kernel<<<MTOK, 128>>>(x, norm1_g, norm1_b, winh, winl);

    // 2. QKV GEMM (100352 x 384) @ (384 x 1152)
    mma_gemm<0><<<dim3(9, MTOK/128), 256, GEMM_SMEM>>>(
        winh, winl, wqh, wql, qkv_b, nullptr, qkvbuf, nullptr, nullptr, 3*CDIM, CDIM);

    // 3. Windowed attention
    attn_kernel<<<dim3(BN, NHEADS), 64>>>(qkvbuf, attnmask, rpb, atth, attl);

    // 4. proj GEMM
    mma_gemm<0><<<dim3(3, MTOK/128), 256, GEMM_SMEM>>>(
        atth, attl, wph, wpl, proj_b, nullptr, projb, nullptr, nullptr, CDIM, CDIM);

    // 5+6. reverse + roll + residual + LN2 (fused)
    mergeln_kernel<<<MTOK, 128>>>(x, projb, norm2_g, norm2_b, y, h2h, h2l);

    // 7. fc1 + GELU (bf16 hi/lo out)
    mma_gemm<1><<<dim3(12, MTOK/128), 256, GEMM_SMEM>>>(
        h2h, h2l, w1h, w1l, fc1_b, nullptr, nullptr, mlph, mlpl, HID, CDIM);

    // 8. fc2 + residual -> d_out
    mma_gemm<2><<<dim3(3, MTOK/128), 256, GEMM_SMEM>>>(
        mlph, mlpl, w2h, w2l, fc2_b, y, (float*)d_out, nullptr, nullptr, CDIM, HID);
}

// round 9
// speedup vs baseline: 2.3926x; 1.0794x over previous
#include <cuda_runtime.h>
#include <cuda_bf16.h>
#include <math.h>
#include <stdint.h>

// ---------------------------------------------------------------------------
// Problem constants
// ---------------------------------------------------------------------------
#define BATCH   32
#define HIMG    56
#define WIMG    56
#define CDIM    384
#define LTOK    (HIMG*WIMG)          // 3136
#define NHEADS  12
#define HD      32
#define WS      7
#define NWIN_T  49
#define SHIFT   3
#define NWX     8
#define NWIN    64
#define BN      (BATCH*NWIN)         // 2048 windows
#define MTOK    (BN*NWIN_T)          // 100352 tokens
#define HID     1536

// ---------------------------------------------------------------------------
// Scratch (device globals)
// ---------------------------------------------------------------------------
__device__ float          g_qkv [(size_t)MTOK * 3 * CDIM];
__device__ float          g_proj[(size_t)MTOK * CDIM];
__device__ float          g_y   [(size_t)MTOK * CDIM];
__device__ __nv_bfloat16  g_win_h[(size_t)MTOK * CDIM];
__device__ __nv_bfloat16  g_win_l[(size_t)MTOK * CDIM];
__device__ __nv_bfloat16  g_att_h[(size_t)MTOK * CDIM];
__device__ __nv_bfloat16  g_att_l[(size_t)MTOK * CDIM];
__device__ __nv_bfloat16  g_h2_h [(size_t)MTOK * CDIM];
__device__ __nv_bfloat16  g_h2_l [(size_t)MTOK * CDIM];
__device__ __nv_bfloat16  g_mlp_h[(size_t)MTOK * HID];
__device__ __nv_bfloat16  g_mlp_l[(size_t)MTOK * HID];
// transposed + split weights: Wt[N][K]
__device__ __nv_bfloat16  g_wq_h[3*CDIM*CDIM], g_wq_l[3*CDIM*CDIM];
__device__ __nv_bfloat16  g_wp_h[CDIM*CDIM],   g_wp_l[CDIM*CDIM];
__device__ __nv_bfloat16  g_w1_h[HID*CDIM],    g_w1_l[HID*CDIM];
__device__ __nv_bfloat16  g_w2_h[CDIM*HID],    g_w2_l[CDIM*HID];

// ---------------------------------------------------------------------------
// Helpers
// ---------------------------------------------------------------------------
static __device__ __forceinline__ uint32_t s2u(const void* p) {
    return (uint32_t)__cvta_generic_to_shared(p);
}
static __device__ __forceinline__ void split_store(__nv_bfloat16* ph, __nv_bfloat16* pl,
                                                   size_t idx, float v) {
    __nv_bfloat16 h = __float2bfloat16(v);
    ph[idx] = h;
    pl[idx] = __float2bfloat16(v - __bfloat162float(h));
}
static __device__ __forceinline__ void split_store2(__nv_bfloat16* ph, __nv_bfloat16* pl,
                                                    size_t idx, float v0, float v1) {
    __nv_bfloat16 h0 = __float2bfloat16(v0), h1 = __float2bfloat16(v1);
    __nv_bfloat162 hv; hv.x = h0; hv.y = h1;
    __nv_bfloat162 lv;
    lv.x = __float2bfloat16(v0 - __bfloat162float(h0));
    lv.y = __float2bfloat16(v1 - __bfloat162float(h1));
    *(__nv_bfloat162*)(ph + idx) = hv;
    *(__nv_bfloat162*)(pl + idx) = lv;
}
static __device__ __forceinline__ void ldm4(uint32_t& d0, uint32_t& d1, uint32_t& d2,
                                            uint32_t& d3, uint32_t a) {
    asm volatile("ldmatrix.sync.aligned.m8n8.x4.shared.b16 {%0,%1,%2,%3},[%4];"
                 : "=r"(d0), "=r"(d1), "=r"(d2), "=r"(d3) : "r"(a));
}
static __device__ __forceinline__ void mma16816(float* c, const uint32_t* a, const uint32_t* b) {
    asm volatile("mma.sync.aligned.m16n8k16.row.col.f32.bf16.bf16.f32 "
                 "{%0,%1,%2,%3},{%4,%5,%6,%7},{%8,%9},{%0,%1,%2,%3};"
                 : "+f"(c[0]), "+f"(c[1]), "+f"(c[2]), "+f"(c[3])
                 : "r"(a[0]), "r"(a[1]), "r"(a[2]), "r"(a[3]), "r"(b[0]), "r"(b[1]));
}
static __device__ __forceinline__ void cpa16(uint32_t dst, const void* src) {
    asm volatile("cp.async.cg.shared.global [%0], [%1], 16;"
                 :: "r"(dst), "l"(src) : "memory");
}

// ---------------------------------------------------------------------------
// HMMA GEMM: C[M,N] = (Ah+Al)[M,K] @ (Bh+Bl)[N,K]^T  (bf16x3 compensated)
// 128x128 block tile, BK=32, 8 warps (2x4), warp tile 64x32.
// XOR-swizzled 64B-row smem (no padding), 3-stage cp.async, 2 CTAs/SM,
// single __syncthreads per chunk.
// Swizzle: 16B granule g at row r lives at g ^ ((r>>1)&3).
// EPI 0: fp32 out + bias | 1: bias+GELU -> bf16 hi/lo | 2: bias+residual -> fp32
// ---------------------------------------------------------------------------
#define TILE_B   (128*64)                 // 8192 bytes per tile (128 rows x 64B)
#define STAGE_B  (4*TILE_B)               // Ah,Al,Bh,Bl : 32768 bytes
#define NSTAGE   3
#define GEMM_SMEM (NSTAGE*STAGE_B)        // 98304 bytes

template <int EPI>
__global__ __launch_bounds__(256, 2)
void mma_gemm(const __nv_bfloat16* __restrict__ Ah, const __nv_bfloat16* __restrict__ Al,
              const __nv_bfloat16* __restrict__ Bh, const __nv_bfloat16* __restrict__ Bl,
              const float* __restrict__ bias, const float* __restrict__ res,
              float* __restrict__ Cf, __nv_bfloat16* __restrict__ Ch,
              __nv_bfloat16* __restrict__ Cl, int N, int K)
{
    extern __shared__ char sm[];
    const int tid  = threadIdx.x, lane = tid & 31, warp = tid >> 5;
    const int m0 = blockIdx.y * 128, n0 = blockIdx.x * 128;
    const int wm = (warp >> 2) * 64, wn = (warp & 3) * 32;

    // global source: each thread owns rows r0 and r0+64, granule g0 (8 bf16 = 16B)
    const int r0 = tid >> 2, g0 = tid & 3;
    const int c0 = g0 * 8;
    const __nv_bfloat16* pAh = Ah + (size_t)(m0 + r0) * K + c0;
    const __nv_bfloat16* pAl = Al + (size_t)(m0 + r0) * K + c0;
    const __nv_bfloat16* pBh = Bh + (size_t)(n0 + r0) * K + c0;
    const __nv_bfloat16* pBl = Bl + (size_t)(n0 + r0) * K + c0;
    const size_t rstep = (size_t)64 * K;
    // swizzled store offsets (row+64 keeps the same swizzle bits: 32 ≡ 0 mod 4)
    const uint32_t sw0 = ((uint32_t)r0 >> 1) & 3;
    const uint32_t so0 = (uint32_t)r0 * 64 + (((uint32_t)g0 ^ sw0) << 4);
    const uint32_t so1 = so0 + 64 * 64;
    const uint32_t smb = s2u(sm);

    const int nch = K >> 5;

    auto issue_stage = [&](int i, int s) {
        int k0 = i << 5;
        uint32_t b = smb + (uint32_t)s * STAGE_B;
        cpa16(b + so0,              pAh + k0);
        cpa16(b + so1,              pAh + rstep + k0);
        cpa16(b + TILE_B + so0,     pAl + k0);
        cpa16(b + TILE_B + so1,     pAl + rstep + k0);
        cpa16(b + 2*TILE_B + so0,   pBh + k0);
        cpa16(b + 2*TILE_B + so1,   pBh + rstep + k0);
        cpa16(b + 3*TILE_B + so0,   pBl + k0);
        cpa16(b + 3*TILE_B + so1,   pBl + rstep + k0);
        asm volatile("cp.async.commit_group;" ::: "memory");
    };

    float acc[4][4][4];
    #pragma unroll
    for (int i = 0; i < 4; i++)
        #pragma unroll
        for (int j = 0; j < 4; j++)
            #pragma unroll
            for (int k = 0; k < 4; k++) acc[i][j][k] = 0.0f;

    // ldmatrix lane addressing (row/granule per lane)
    const int tsel = lane >> 3, rlo = lane & 7;
    const uint32_t rA = (uint32_t)(wm + rlo + (tsel & 1) * 8);
    const uint32_t gA = (uint32_t)(tsel >> 1);
    const uint32_t rB = (uint32_t)(wn + rlo + (tsel >> 1) * 8);
    const uint32_t gB = (uint32_t)(tsel & 1);

    issue_stage(0, 0);
    if (nch > 1) issue_stage(1, 1);

    int stage = 0;
    for (int i = 0; i < nch; i++) {
        if (i + 1 < nch) asm volatile("cp.async.wait_group 1;" ::: "memory");
        else             asm volatile("cp.async.wait_group 0;" ::: "memory");
        __syncthreads();

        if (i + 2 < nch) {
            int s = stage + 2; if (s >= NSTAGE) s -= NSTAGE;
            issue_stage(i + 2, s);
        }

        const uint32_t sb = smb + (uint32_t)stage * STAGE_B;
        #pragma unroll
        for (int kst = 0; kst < 2; kst++) {
            uint32_t bh[4][2], bl[4][2];
            #pragma unroll
            for (int p = 0; p < 2; p++) {
                uint32_t row = rB + p * 16;
                uint32_t sw  = (row >> 1) & 3;
                uint32_t ad  = sb + 2*TILE_B + row * 64 + (((gB + kst*2u) ^ sw) << 4);
                ldm4(bh[2*p][0], bh[2*p][1], bh[2*p+1][0], bh[2*p+1][1], ad);
                ldm4(bl[2*p][0], bl[2*p][1], bl[2*p+1][0], bl[2*p+1][1], ad + TILE_B);
            }
            #pragma unroll
            for (int mf = 0; mf < 4; mf++) {
                uint32_t row = rA + mf * 16;
                uint32_t sw  = (row >> 1) & 3;
                uint32_t ad  = sb + row * 64 + (((gA + kst*2u) ^ sw) << 4);
                uint32_t ah[4], al[4];
                ldm4(ah[0], ah[1], ah[2], ah[3], ad);
                ldm4(al[0], al[1], al[2], al[3], ad + TILE_B);
                #pragma unroll
                for (int nf = 0; nf < 4; nf++) {
                    mma16816(acc[mf][nf], ah, bh[nf]);
                    mma16816(acc[mf][nf], al, bh[nf]);
                    mma16816(acc[mf][nf], ah, bl[nf]);
                }
            }
        }
        stage++; if (stage >= NSTAGE) stage = 0;
    }
    __syncthreads();

    // -- epilogue from accumulator fragments
    const int qr = lane >> 2, qc = (lane & 3) * 2;
    #pragma unroll
    for (int mf = 0; mf < 4; mf++) {
        int row = m0 + wm + mf * 16 + qr;
        #pragma unroll
        for (int nf = 0; nf < 4; nf++) {
            int col = n0 + wn + nf * 8 + qc;
            float b0 = bias[col], b1 = bias[col + 1];
            float v0 = acc[mf][nf][0] + b0, v1 = acc[mf][nf][1] + b1;
            float v2 = acc[mf][nf][2] + b0, v3 = acc[mf][nf][3] + b1;
            if (EPI == 0) {
                *(float2*)(Cf + (size_t)row * N + col)       = make_float2(v0, v1);
                *(float2*)(Cf + (size_t)(row + 8) * N + col) = make_float2(v2, v3);
            } else if (EPI == 1) {
                v0 = 0.5f * v0 * (1.0f + erff(v0 * 0.70710678118654752f));
                v1 = 0.5f * v1 * (1.0f + erff(v1 * 0.70710678118654752f));
                v2 = 0.5f * v2 * (1.0f + erff(v2 * 0.70710678118654752f));
                v3 = 0.5f * v3 * (1.0f + erff(v3 * 0.70710678118654752f));
                split_store2(Ch, Cl, (size_t)row * N + col,       v0, v1);
                split_store2(Ch, Cl, (size_t)(row + 8) * N + col, v2, v3);
            } else {
                float2 r0v = *(const float2*)(res + (size_t)row * N + col);
                float2 r1v = *(const float2*)(res + (size_t)(row + 8) * N + col);
                *(float2*)(Cf + (size_t)row * N + col)       = make_float2(v0 + r0v.x, v1 + r0v.y);
                *(float2*)(Cf + (size_t)(row + 8) * N + col) = make_float2(v2 + r1v.x, v3 + r1v.y);
            }
        }
    }
}

// ---------------------------------------------------------------------------
// Weight transpose + bf16 hi/lo split: W[K][N] fp32 -> Wt_hi/lo[N][K]
// 32x32 smem-tiled transpose; both read and write coalesced.
// ---------------------------------------------------------------------------
__global__ __launch_bounds__(256)
void wsplit_kernel(const float* __restrict__ W, __nv_bfloat16* __restrict__ Hh,
                   __nv_bfloat16* __restrict__ Hl, int K, int N)
{
    __shared__ float t[32][33];
    int tx = threadIdx.x & 31, ty = threadIdx.x >> 5;   // 32 x 8
    int kb = blockIdx.y * 32, nb = blockIdx.x * 32;
    #pragma unroll
    for (int j = ty; j < 32; j += 8)
        t[j][tx] = W[(size_t)(kb + j) * N + nb + tx];
    __syncthreads();
    #pragma unroll
    for (int j = ty; j < 32; j += 8)
        split_store(Hh, Hl, (size_t)(nb + j) * K + kb + tx, t[tx][j]);
}

// ---------------------------------------------------------------------------
// LN1 + shift + window-partition gather, outputs bf16 hi/lo
// ---------------------------------------------------------------------------
__global__ __launch_bounds__(128)
void ln1_kernel(const float* __restrict__ x, const float* __restrict__ gam,
                const float* __restrict__ bet, __nv_bfloat16* __restrict__ oh,
                __nv_bfloat16* __restrict__ ol)
{
    int tr = blockIdx.x;
    int bn = tr / NWIN_T;
    int n  = tr - bn * NWIN_T;
    int b  = bn / NWIN;
    int wi = bn - b * NWIN;
    int wy = wi / NWX, wx = wi - wy * NWX;
    int r  = n / WS,   cc = n - r * WS;
    int hs = (wy * WS + r  + SHIFT) % HIMG;
    int ws2= (wx * WS + cc + SHIFT) % WIMG;
    int src = b * LTOK + hs * WIMG + ws2;

    const float* xin = x + (size_t)src * CDIM;
    int tid = threadIdx.x;
    float v0 = xin[tid], v1 = xin[tid + 128], v2 = xin[tid + 256];
    float s  = v0 + v1 + v2;
    float ss = v0*v0 + v1*v1 + v2*v2;
    #pragma unroll
    for (int o = 16; o > 0; o >>= 1) {
        s  += __shfl_down_sync(0xffffffffu, s,  o);
        ss += __shfl_down_sync(0xffffffffu, ss, o);
    }
    __shared__ float red[8];
    __shared__ float mbv[2];
    int w = tid >> 5, l = tid & 31;
    if (l == 0) { red[w] = s; red[4 + w] = ss; }
    __syncthreads();
    if (tid == 0) {
        float S  = red[0] + red[1] + red[2] + red[3];
        float SS = red[4] + red[5] + red[6] + red[7];
        float mean = S * (1.0f / CDIM);
        float var  = SS * (1.0f / CDIM) - mean * mean;
        mbv[0] = mean; mbv[1] = rsqrtf(var + 1e-5f);
    }
    __syncthreads();
    float mean = mbv[0], rstd = mbv[1];
    size_t ob = (size_t)tr * CDIM;
    split_store(oh, ol, ob + tid,       (v0 - mean) * rstd * gam[tid]       + bet[tid]);
    split_store(oh, ol, ob + tid + 128, (v1 - mean) * rstd * gam[tid + 128] + bet[tid + 128]);
    split_store(oh, ol, ob + tid + 256, (v2 - mean) * rstd * gam[tid + 256] + bet[tid + 256]);
}

// ---------------------------------------------------------------------------
// Fused: window-reverse + roll + residual, then LN2
// ---------------------------------------------------------------------------
__global__ __launch_bounds__(128)
void mergeln_kernel(const float* __restrict__ x, const float* __restrict__ proj,
                    const float* __restrict__ gam, const float* __restrict__ bet,
                    float* __restrict__ y, __nv_bfloat16* __restrict__ oh,
                    __nv_bfloat16* __restrict__ ol)
{
    int tr = blockIdx.x;
    int b = tr / LTOK, pos = tr - b * LTOK;
    int i = pos / WIMG, j = pos - i * WIMG;
    int ii = (i + HIMG - SHIFT) % HIMG;
    int jj = (j + WIMG - SHIFT) % WIMG;
    int wr = (b * NWIN + (ii / WS) * NWX + (jj / WS)) * NWIN_T + (ii % WS) * WS + (jj % WS);

    const float* xp = x    + (size_t)tr * CDIM;
    const float* pp = proj + (size_t)wr * CDIM;
    int tid = threadIdx.x;
    float v0 = xp[tid]       + pp[tid];
    float v1 = xp[tid + 128] + pp[tid + 128];
    float v2 = xp[tid + 256] + pp[tid + 256];

    float* yp = y + (size_t)tr * CDIM;
    yp[tid] = v0; yp[tid + 128] = v1; yp[tid + 256] = v2;

    float s  = v0 + v1 + v2;
    float ss = v0*v0 + v1*v1 + v2*v2;
    #pragma unroll
    for (int o = 16; o > 0; o >>= 1) {
        s  += __shfl_down_sync(0xffffffffu, s,  o);
        ss += __shfl_down_sync(0xffffffffu, ss, o);
    }
    __shared__ float red[8];
    __shared__ float mbv[2];
    int w = tid >> 5, l = tid & 31;
    if (l == 0) { red[w] = s; red[4 + w] = ss; }
    __syncthreads();
    if (tid == 0) {
        float S  = red[0] + red[1] + red[2] + red[3];
        float SS = red[4] + red[5] + red[6] + red[7];
        float mean = S * (1.0f / CDIM);
        float var  = SS * (1.0f / CDIM) - mean * mean;
        mbv[0] = mean; mbv[1] = rsqrtf(var + 1e-5f);
    }
    __syncthreads();
    float mean = mbv[0], rstd = mbv[1];
    size_t ob = (size_t)tr * CDIM;
    split_store(oh, ol, ob + tid,       (v0 - mean) * rstd * gam[tid]       + bet[tid]);
    split_store(oh, ol, ob + tid + 128, (v1 - mean) * rstd * gam[tid + 128] + bet[tid + 128]);
    split_store(oh, ol, ob + tid + 256, (v2 - mean) * rstd * gam[tid + 256] + bet[tid + 256]);
}

// ---------------------------------------------------------------------------
// Windowed attention: one block (64 thr) per (window, head).
// Thread n keeps Q row / output row in registers; K/V rows via broadcast LDS.128.
// ---------------------------------------------------------------------------
#define SST 50   // padded logits stride
__global__ __launch_bounds__(64)
void attn_kernel(const float* __restrict__ qkv, const float* __restrict__ mask,
                 const float* __restrict__ rpb, __nv_bfloat16* __restrict__ oh,
                 __nv_bfloat16* __restrict__ ol)
{
    __shared__ float Qs[NWIN_T * 32];
    __shared__ float Ks[NWIN_T * 32];
    __shared__ float Vs[NWIN_T * 32];
    __shared__ float Ss[NWIN_T * SST];

    int bn = blockIdx.x, h = blockIdx.y, tid = threadIdx.x;
    const float scale = 0.1767766952966369f;   // 32^-0.5

    size_t basep = (size_t)bn * NWIN_T * (3 * CDIM) + h * HD;
    for (int idx = tid; idx < NWIN_T * 8; idx += 64) {
        int n = idx >> 3, q = idx & 7;
        const float* rowp = qkv + basep + (size_t)n * (3 * CDIM);
        float4 qv = *(const float4*)(rowp + q * 4);
        qv.x *= scale; qv.y *= scale; qv.z *= scale; qv.w *= scale;
        *(float4*)&Qs[n * 32 + q * 4] = qv;
        *(float4*)&Ks[n * 32 + q * 4] = *(const float4*)(rowp + CDIM + q * 4);
        *(float4*)&Vs[n * 32 + q * 4] = *(const float4*)(rowp + 2 * CDIM + q * 4);
    }
    __syncthreads();

    if (tid < NWIN_T) {
        const int n = tid;
        const float* mw = mask + (bn & (NWIN - 1)) * (NWIN_T * NWIN_T) + n * NWIN_T;
        const int r1 = n / WS, c1 = n - r1 * WS;

        float q[32];
        #pragma unroll
        for (int i = 0; i < 8; i++) {
            float4 v = *(const float4*)&Qs[n * 32 + i * 4];
            q[i*4+0] = v.x; q[i*4+1] = v.y; q[i*4+2] = v.z; q[i*4+3] = v.w;
        }

        for (int m = 0; m < NWIN_T; m++) {
            float acc = 0.0f;
            #pragma unroll
            for (int i = 0; i < 8; i++) {
                float4 kv = *(const float4*)&Ks[m * 32 + i * 4];
                acc += q[i*4+0]*kv.x + q[i*4+1]*kv.y + q[i*4+2]*kv.z + q[i*4+3]*kv.w;
            }
            int r2 = m / WS, c2 = m - r2 * WS;
            int rel = (r1 - r2 + WS - 1) * (2 * WS - 1) + (c1 - c2 + WS - 1);
            Ss[n * SST + m] = acc + rpb[rel * NHEADS + h] + mw[m];
        }

        float mx = -1e30f;
        for (int m = 0; m < NWIN_T; m++) mx = fmaxf(mx, Ss[n * SST + m]);
        float sum = 0.0f;
        for (int m = 0; m < NWIN_T; m++) {
            float e = __expf(Ss[n * SST + m] - mx);
            Ss[n * SST + m] = e; sum += e;
        }
        float inv = 1.0f / sum;

        float acc[32];
        #pragma unroll
        for (int i = 0; i < 32; i++) acc[i] = 0.0f;
        for (int m = 0; m < NWIN_T; m++) {
            float p = Ss[n * SST + m];
            #pragma unroll
            for (int i = 0; i < 8; i++) {
                float4 vv = *(const float4*)&Vs[m * 32 + i * 4];
                acc[i*4+0] += p * vv.x; acc[i*4+1] += p * vv.y;
                acc[i*4+2] += p * vv.z; acc[i*4+3] += p * vv.w;
            }
        }
        size_t ob = (size_t)(bn * NWIN_T + n) * CDIM + h * HD;
        #pragma unroll
        for (int i = 0; i < 16; i++)
            split_store2(oh, ol, ob + 2*i, acc[2*i] * inv, acc[2*i+1] * inv);
    }
}

// ---------------------------------------------------------------------------
// Launch
// ---------------------------------------------------------------------------
extern "C" void kernel_launch(void* const* d_in, const int* in_sizes, int n_in,
                              void* d_out, int out_size)
{
    const float* x        = (const float*)d_in[0];
    const float* attnmask = (const float*)d_in[1];
    const float* norm1_g  = (const float*)d_in[2];
    const float* norm1_b  = (const float*)d_in[3];
    const float* qkv_w    = (const float*)d_in[4];
    const float* qkv_b    = (const float*)d_in[5];
    const float* rpb      = (const float*)d_in[6];
    const float* proj_w   = (const float*)d_in[7];
    const float* proj_b   = (const float*)d_in[8];
    const float* norm2_g  = (const float*)d_in[9];
    const float* norm2_b  = (const float*)d_in[10];
    const float* fc1_w    = (const float*)d_in[11];
    const float* fc1_b    = (const float*)d_in[12];
    const float* fc2_w    = (const float*)d_in[13];
    const float* fc2_b    = (const float*)d_in[14];
    (void)in_sizes; (void)n_in; (void)out_size;

    float *qkvbuf, *projb, *y;
    __nv_bfloat16 *winh, *winl, *atth, *attl, *h2h, *h2l, *mlph, *mlpl;
    __nv_bfloat16 *wqh, *wql, *wph, *wpl, *w1h, *w1l, *w2h, *w2l;
    cudaGetSymbolAddress((void**)&qkvbuf, g_qkv);
    cudaGetSymbolAddress((void**)&projb,  g_proj);
    cudaGetSymbolAddress((void**)&y,      g_y);
    cudaGetSymbolAddress((void**)&winh,   g_win_h); cudaGetSymbolAddress((void**)&winl, g_win_l);
    cudaGetSymbolAddress((void**)&atth,   g_att_h); cudaGetSymbolAddress((void**)&attl, g_att_l);
    cudaGetSymbolAddress((void**)&h2h,    g_h2_h);  cudaGetSymbolAddress((void**)&h2l,  g_h2_l);
    cudaGetSymbolAddress((void**)&mlph,   g_mlp_h); cudaGetSymbolAddress((void**)&mlpl, g_mlp_l);
    cudaGetSymbolAddress((void**)&wqh,    g_wq_h);  cudaGetSymbolAddress((void**)&wql,  g_wq_l);
    cudaGetSymbolAddress((void**)&wph,    g_wp_h);  cudaGetSymbolAddress((void**)&wpl,  g_wp_l);
    cudaGetSymbolAddress((void**)&w1h,    g_w1_h);  cudaGetSymbolAddress((void**)&w1l,  g_w1_l);
    cudaGetSymbolAddress((void**)&w2h,    g_w2_h);  cudaGetSymbolAddress((void**)&w2l,  g_w2_l);

    cudaFuncSetAttribute(mma_gemm<0>, cudaFuncAttributeMaxDynamicSharedMemorySize, GEMM_SMEM);
    cudaFuncSetAttribute(mma_gemm<1>, cudaFuncAttributeMaxDynamicSharedMemorySize, GEMM_SMEM);
    cudaFuncSetAttribute(mma_gemm<2>, cudaFuncAttributeMaxDynamicSharedMemorySize, GEMM_SMEM);

    // 0. weight transpose + split (tiled, coalesced)
    wsplit_kernel<<<dim3(3*CDIM/32, CDIM/32), 256>>>(qkv_w,  wqh, wql, CDIM, 3*CDIM);
    wsplit_kernel<<<dim3(CDIM/32,   CDIM/32), 256>>>(proj_w, wph, wpl, CDIM, CDIM);
    wsplit_kernel<<<dim3(HID/32,    CDIM/32), 256>>>(fc1_w,  w1h, w1l, CDIM, HID);
    wsplit_kernel<<<dim3(CDIM/32,   HID/32),  256>>>(fc2_w,  w2h, w2l, HID,  CDIM);

    // 1. LN1 + shift + window partition (bf16 hi/lo)
    ln1_kernel<<<MTOK, 128>>>(x, norm1_g, norm1_b, winh, winl);

    // 2. QKV GEMM (100352 x 384) @ (384 x 1152)
    mma_gemm<0><<<dim3(9, MTOK/128), 256, GEMM_SMEM>>>(
        winh, winl, wqh, wql, qkv_b, nullptr, qkvbuf, nullptr, nullptr, 3*CDIM, CDIM);

    // 3. Windowed attention
    attn_kernel<<<dim3(BN, NHEADS), 64>>>(qkvbuf, attnmask, rpb, atth, attl);

    // 4. proj GEMM
    mma_gemm<0><<<dim3(3, MTOK/128), 256, GEMM_SMEM>>>(
        atth, attl, wph, wpl, proj_b, nullptr, projb, nullptr, nullptr, CDIM, CDIM);

    // 5+6. reverse + roll + residual + LN2 (fused)
    mergeln_kernel<<<MTOK, 128>>>(x, projb, norm2_g, norm2_b, y, h2h, h2l);

    // 7. fc1 + GELU (bf16 hi/lo out)
    mma_gemm<1><<<dim3(12, MTOK/128), 256, GEMM_SMEM>>>(
        h2h, h2l, w1h, w1l, fc1_b, nullptr, nullptr, mlph, mlpl, HID, CDIM);

    // 8. fc2 + residual -> d_out
    mma_gemm<2><<<dim3(3, MTOK/128), 256, GEMM_SMEM>>>(
        mlph, mlpl, w2h, w2l, fc2_b, y, (float*)d_out, nullptr, nullptr, CDIM, HID);
}

// round 10
// speedup vs baseline: 2.6625x; 1.1128x over previous
#include <cuda_runtime.h>
#include <cuda_bf16.h>
#include <math.h>
#include <stdint.h>

// ---------------------------------------------------------------------------
// Problem constants
// ---------------------------------------------------------------------------
#define BATCH   32
#define HIMG    56
#define WIMG    56
#define CDIM    384
#define LTOK    (HIMG*WIMG)          // 3136
#define NHEADS  12
#define HD      32
#define WS      7
#define NWIN_T  49
#define SHIFT   3
#define NWX     8
#define NWIN    64
#define BN      (BATCH*NWIN)         // 2048 windows
#define MTOK    (BN*NWIN_T)          // 100352 tokens
#define HID     1536

// ---------------------------------------------------------------------------
// Scratch (device globals) — all fp32 (tf32-rounded where GEMM operands)
// ---------------------------------------------------------------------------
__device__ float g_qkv [(size_t)MTOK * 3 * CDIM];
__device__ float g_proj[(size_t)MTOK * CDIM];
__device__ float g_y   [(size_t)MTOK * CDIM];
__device__ float g_win [(size_t)MTOK * CDIM];
__device__ float g_att [(size_t)MTOK * CDIM];
__device__ float g_h2  [(size_t)MTOK * CDIM];
__device__ float g_mlp [(size_t)MTOK * HID];
// transposed weights Wt[N][K], tf32-rounded
__device__ float g_wq[3*CDIM*CDIM];
__device__ float g_wp[CDIM*CDIM];
__device__ float g_w1[HID*CDIM];
__device__ float g_w2[CDIM*HID];

// ---------------------------------------------------------------------------
// Helpers
// ---------------------------------------------------------------------------
static __device__ __forceinline__ uint32_t s2u(const void* p) {
    return (uint32_t)__cvta_generic_to_shared(p);
}
static __device__ __forceinline__ float tf32r(float f) {
    uint32_t r; asm("cvt.rna.tf32.f32 %0, %1;" : "=r"(r) : "f"(f));
    return __uint_as_float(r);
}
static __device__ __forceinline__ void ldm4(uint32_t& d0, uint32_t& d1, uint32_t& d2,
                                            uint32_t& d3, uint32_t a) {
    asm volatile("ldmatrix.sync.aligned.m8n8.x4.shared.b16 {%0,%1,%2,%3},[%4];"
                 : "=r"(d0), "=r"(d1), "=r"(d2), "=r"(d3) : "r"(a));
}
static __device__ __forceinline__ void mma_tf32(float* c, const uint32_t* a, const uint32_t* b) {
    asm volatile("mma.sync.aligned.m16n8k8.row.col.f32.tf32.tf32.f32 "
                 "{%0,%1,%2,%3},{%4,%5,%6,%7},{%8,%9},{%0,%1,%2,%3};"
                 : "+f"(c[0]), "+f"(c[1]), "+f"(c[2]), "+f"(c[3])
                 : "r"(a[0]), "r"(a[1]), "r"(a[2]), "r"(a[3]), "r"(b[0]), "r"(b[1]));
}
static __device__ __forceinline__ void cpa16(uint32_t dst, const void* src) {
    asm volatile("cp.async.cg.shared.global [%0], [%1], 16;"
                 :: "r"(dst), "l"(src) : "memory");
}

// ---------------------------------------------------------------------------
// tf32 MMA GEMM: C[M,N] = A[M,K] @ B[N,K]^T, single pass.
// 128x128 block tile, BK=32, 8 warps (2x4), warp tile 64x32.
// fp32 smem rows of 128B (8 granules), swizzle g ^= row&7.
// 3-stage cp.async, 2 CTAs/SM, one __syncthreads per chunk.
// Fragments via b16-ldmatrix (8x8 b16 tile == 8 rows x 4 fp32).
// EPI 0: fp32 + bias | 1: bias+GELU -> tf32-rounded fp32 | 2: bias+residual -> fp32
// ---------------------------------------------------------------------------
#define TILE_B   (128*128)                // 16384 bytes (128 rows x 128B)
#define STAGE_B  (2*TILE_B)               // A + B : 32768 bytes
#define NSTAGE   3
#define GEMM_SMEM (NSTAGE*STAGE_B)        // 98304 bytes

template <int EPI>
__global__ __launch_bounds__(256, 2)
void mma_gemm(const float* __restrict__ A, const float* __restrict__ B,
              const float* __restrict__ bias, const float* __restrict__ res,
              float* __restrict__ Cf, int N, int K)
{
    extern __shared__ char sm[];
    const int tid  = threadIdx.x, lane = tid & 31, warp = tid >> 5;
    const int m0 = blockIdx.y * 128, n0 = blockIdx.x * 128;
    const int wm = (warp >> 2) * 64, wn = (warp & 3) * 32;

    // copy setup: thread owns row cr, granules cg0..cg0+3 (16B = 4 fp32 each)
    const int cr  = tid >> 1;
    const int cg0 = (tid & 1) * 4;
    const float* pA = A + (size_t)(m0 + cr) * K;
    const float* pB = B + (size_t)(n0 + cr) * K;
    uint32_t so[4];
    #pragma unroll
    for (int j = 0; j < 4; j++)
        so[j] = (uint32_t)cr * 128 + ((((uint32_t)(cg0 + j)) ^ ((uint32_t)cr & 7)) << 4);
    const uint32_t smb = s2u(sm);
    const int nch = K >> 5;

    auto issue_stage = [&](int i, int s) {
        int k0 = i << 5;
        uint32_t b = smb + (uint32_t)s * STAGE_B;
        #pragma unroll
        for (int j = 0; j < 4; j++) {
            cpa16(b + so[j],          pA + k0 + (cg0 + j) * 4);
            cpa16(b + TILE_B + so[j], pB + k0 + (cg0 + j) * 4);
        }
        asm volatile("cp.async.commit_group;" ::: "memory");
    };

    float acc[4][4][4];
    #pragma unroll
    for (int i = 0; i < 4; i++)
        #pragma unroll
        for (int j = 0; j < 4; j++)
            #pragma unroll
            for (int k = 0; k < 4; k++) acc[i][j][k] = 0.0f;

    // ldmatrix lane addressing. row&7 == rlo for every tile (all bases mult of 8/16).
    const int tsel = lane >> 3, rlo = lane & 7;
    const uint32_t gA = (uint32_t)(tsel >> 1);  // A granule bit
    const uint32_t gB = (uint32_t)(tsel & 1);   // B granule bit
    uint32_t aoffm[4], boffp[2];
    #pragma unroll
    for (int mf = 0; mf < 4; mf++)
        aoffm[mf] = (uint32_t)(wm + mf * 16 + rlo + (tsel & 1) * 8) * 128;
    #pragma unroll
    for (int p = 0; p < 2; p++)
        boffp[p] = (uint32_t)TILE_B + (uint32_t)(wn + p * 16 + rlo + (tsel >> 1) * 8) * 128;

    issue_stage(0, 0);
    if (nch > 1) issue_stage(1, 1);

    int stage = 0;
    for (int i = 0; i < nch; i++) {
        if (i + 1 < nch) asm volatile("cp.async.wait_group 1;" ::: "memory");
        else             asm volatile("cp.async.wait_group 0;" ::: "memory");
        __syncthreads();

        if (i + 2 < nch) {
            int s = stage + 2; if (s >= NSTAGE) s -= NSTAGE;
            issue_stage(i + 2, s);
        }

        const uint32_t sb = smb + (uint32_t)stage * STAGE_B;
        #pragma unroll
        for (int kst = 0; kst < 4; kst++) {
            const uint32_t oA = (((2u * kst + gA) ^ (uint32_t)rlo) << 4);
            const uint32_t oB = (((2u * kst + gB) ^ (uint32_t)rlo) << 4);
            uint32_t bfr[4][2];
            #pragma unroll
            for (int p = 0; p < 2; p++)
                ldm4(bfr[2*p][0], bfr[2*p][1], bfr[2*p+1][0], bfr[2*p+1][1],
                     sb + boffp[p] + oB);
            #pragma unroll
            for (int mf = 0; mf < 4; mf++) {
                uint32_t afr[4];
                ldm4(afr[0], afr[1], afr[2], afr[3], sb + aoffm[mf] + oA);
                #pragma unroll
                for (int nf = 0; nf < 4; nf++)
                    mma_tf32(acc[mf][nf], afr, bfr[nf]);
            }
        }
        stage++; if (stage >= NSTAGE) stage = 0;
    }
    __syncthreads();

    // -- epilogue from accumulator fragments (same layout as m16n8k16)
    const int qr = lane >> 2, qc = (lane & 3) * 2;
    #pragma unroll
    for (int mf = 0; mf < 4; mf++) {
        int row = m0 + wm + mf * 16 + qr;
        #pragma unroll
        for (int nf = 0; nf < 4; nf++) {
            int col = n0 + wn + nf * 8 + qc;
            float b0 = bias[col], b1 = bias[col + 1];
            float v0 = acc[mf][nf][0] + b0, v1 = acc[mf][nf][1] + b1;
            float v2 = acc[mf][nf][2] + b0, v3 = acc[mf][nf][3] + b1;
            if (EPI == 0) {
                *(float2*)(Cf + (size_t)row * N + col)       = make_float2(v0, v1);
                *(float2*)(Cf + (size_t)(row + 8) * N + col) = make_float2(v2, v3);
            } else if (EPI == 1) {
                v0 = 0.5f * v0 * (1.0f + erff(v0 * 0.70710678118654752f));
                v1 = 0.5f * v1 * (1.0f + erff(v1 * 0.70710678118654752f));
                v2 = 0.5f * v2 * (1.0f + erff(v2 * 0.70710678118654752f));
                v3 = 0.5f * v3 * (1.0f + erff(v3 * 0.70710678118654752f));
                *(float2*)(Cf + (size_t)row * N + col)       = make_float2(tf32r(v0), tf32r(v1));
                *(float2*)(Cf + (size_t)(row + 8) * N + col) = make_float2(tf32r(v2), tf32r(v3));
            } else {
                float2 r0v = *(const float2*)(res + (size_t)row * N + col);
                float2 r1v = *(const float2*)(res + (size_t)(row + 8) * N + col);
                *(float2*)(Cf + (size_t)row * N + col)       = make_float2(v0 + r0v.x, v1 + r0v.y);
                *(float2*)(Cf + (size_t)(row + 8) * N + col) = make_float2(v2 + r1v.x, v3 + r1v.y);
            }
        }
    }
}

// ---------------------------------------------------------------------------
// Weight transpose + tf32 round: W[K][N] fp32 -> Wt[N][K]
// ---------------------------------------------------------------------------
__global__ __launch_bounds__(256)
void wtrans_kernel(const float* __restrict__ W, float* __restrict__ Wt, int K, int N)
{
    __shared__ float t[32][33];
    int tx = threadIdx.x & 31, ty = threadIdx.x >> 5;   // 32 x 8
    int kb = blockIdx.y * 32, nb = blockIdx.x * 32;
    #pragma unroll
    for (int j = ty; j < 32; j += 8)
        t[j][tx] = W[(size_t)(kb + j) * N + nb + tx];
    __syncthreads();
    #pragma unroll
    for (int j = ty; j < 32; j += 8)
        Wt[(size_t)(nb + j) * K + kb + tx] = tf32r(t[tx][j]);
}

// ---------------------------------------------------------------------------
// LN1 + shift + window-partition gather -> tf32-rounded fp32
// ---------------------------------------------------------------------------
__global__ __launch_bounds__(128)
void ln1_kernel(const float* __restrict__ x, const float* __restrict__ gam,
                const float* __restrict__ bet, float* __restrict__ out)
{
    int tr = blockIdx.x;
    int bn = tr / NWIN_T;
    int n  = tr - bn * NWIN_T;
    int b  = bn / NWIN;
    int wi = bn - b * NWIN;
    int wy = wi / NWX, wx = wi - wy * NWX;
    int r  = n / WS,   cc = n - r * WS;
    int hs = (wy * WS + r  + SHIFT) % HIMG;
    int ws2= (wx * WS + cc + SHIFT) % WIMG;
    int src = b * LTOK + hs * WIMG + ws2;

    const float* xin = x + (size_t)src * CDIM;
    int tid = threadIdx.x;
    float v0 = xin[tid], v1 = xin[tid + 128], v2 = xin[tid + 256];
    float s  = v0 + v1 + v2;
    float ss = v0*v0 + v1*v1 + v2*v2;
    #pragma unroll
    for (int o = 16; o > 0; o >>= 1) {
        s  += __shfl_down_sync(0xffffffffu, s,  o);
        ss += __shfl_down_sync(0xffffffffu, ss, o);
    }
    __shared__ float red[8];
    __shared__ float mbv[2];
    int w = tid >> 5, l = tid & 31;
    if (l == 0) { red[w] = s; red[4 + w] = ss; }
    __syncthreads();
    if (tid == 0) {
        float S  = red[0] + red[1] + red[2] + red[3];
        float SS = red[4] + red[5] + red[6] + red[7];
        float mean = S * (1.0f / CDIM);
        float var  = SS * (1.0f / CDIM) - mean * mean;
        mbv[0] = mean; mbv[1] = rsqrtf(var + 1e-5f);
    }
    __syncthreads();
    float mean = mbv[0], rstd = mbv[1];
    float* o = out + (size_t)tr * CDIM;
    o[tid]       = tf32r((v0 - mean) * rstd * gam[tid]       + bet[tid]);
    o[tid + 128] = tf32r((v1 - mean) * rstd * gam[tid + 128] + bet[tid + 128]);
    o[tid + 256] = tf32r((v2 - mean) * rstd * gam[tid + 256] + bet[tid + 256]);
}

// ---------------------------------------------------------------------------
// Fused: window-reverse + roll + residual (y exact fp32), then LN2 -> tf32 fp32
// ---------------------------------------------------------------------------
__global__ __launch_bounds__(128)
void mergeln_kernel(const float* __restrict__ x, const float* __restrict__ proj,
                    const float* __restrict__ gam, const float* __restrict__ bet,
                    float* __restrict__ y, float* __restrict__ out)
{
    int tr = blockIdx.x;
    int b = tr / LTOK, pos = tr - b * LTOK;
    int i = pos / WIMG, j = pos - i * WIMG;
    int ii = (i + HIMG - SHIFT) % HIMG;
    int jj = (j + WIMG - SHIFT) % WIMG;
    int wr = (b * NWIN + (ii / WS) * NWX + (jj / WS)) * NWIN_T + (ii % WS) * WS + (jj % WS);

    const float* xp = x    + (size_t)tr * CDIM;
    const float* pp = proj + (size_t)wr * CDIM;
    int tid = threadIdx.x;
    float v0 = xp[tid]       + pp[tid];
    float v1 = xp[tid + 128] + pp[tid + 128];
    float v2 = xp[tid + 256] + pp[tid + 256];

    float* yp = y + (size_t)tr * CDIM;
    yp[tid] = v0; yp[tid + 128] = v1; yp[tid + 256] = v2;

    float s  = v0 + v1 + v2;
    float ss = v0*v0 + v1*v1 + v2*v2;
    #pragma unroll
    for (int o = 16; o > 0; o >>= 1) {
        s  += __shfl_down_sync(0xffffffffu, s,  o);
        ss += __shfl_down_sync(0xffffffffu, ss, o);
    }
    __shared__ float red[8];
    __shared__ float mbv[2];
    int w = tid >> 5, l = tid & 31;
    if (l == 0) { red[w] = s; red[4 + w] = ss; }
    __syncthreads();
    if (tid == 0) {
        float S  = red[0] + red[1] + red[2] + red[3];
        float SS = red[4] + red[5] + red[6] + red[7];
        float mean = S * (1.0f / CDIM);
        float var  = SS * (1.0f / CDIM) - mean * mean;
        mbv[0] = mean; mbv[1] = rsqrtf(var + 1e-5f);
    }
    __syncthreads();
    float mean = mbv[0], rstd = mbv[1];
    float* o = out + (size_t)tr * CDIM;
    o[tid]       = tf32r((v0 - mean) * rstd * gam[tid]       + bet[tid]);
    o[tid + 128] = tf32r((v1 - mean) * rstd * gam[tid + 128] + bet[tid + 128]);
    o[tid + 256] = tf32r((v2 - mean) * rstd * gam[tid + 256] + bet[tid + 256]);
}

// ---------------------------------------------------------------------------
// Windowed attention: one block (64 thr) per (window, head).
// Thread n keeps Q row / output row in registers; K/V via broadcast LDS.128.
// Output tf32-rounded fp32.
// ---------------------------------------------------------------------------
#define SST 50   // padded logits stride
__global__ __launch_bounds__(64)
void attn_kernel(const float* __restrict__ qkv, const float* __restrict__ mask,
                 const float* __restrict__ rpb, float* __restrict__ outp)
{
    __shared__ float Qs[NWIN_T * 32];
    __shared__ float Ks[NWIN_T * 32];
    __shared__ float Vs[NWIN_T * 32];
    __shared__ float Ss[NWIN_T * SST];

    int bn = blockIdx.x, h = blockIdx.y, tid = threadIdx.x;
    const float scale = 0.1767766952966369f;   // 32^-0.5

    size_t basep = (size_t)bn * NWIN_T * (3 * CDIM) + h * HD;
    for (int idx = tid; idx < NWIN_T * 8; idx += 64) {
        int n = idx >> 3, q = idx & 7;
        const float* rowp = qkv + basep + (size_t)n * (3 * CDIM);
        float4 qv = *(const float4*)(rowp + q * 4);
        qv.x *= scale; qv.y *= scale; qv.z *= scale; qv.w *= scale;
        *(float4*)&Qs[n * 32 + q * 4] = qv;
        *(float4*)&Ks[n * 32 + q * 4] = *(const float4*)(rowp + CDIM + q * 4);
        *(float4*)&Vs[n * 32 + q * 4] = *(const float4*)(rowp + 2 * CDIM + q * 4);
    }
    __syncthreads();

    if (tid < NWIN_T) {
        const int n = tid;
        const float* mw = mask + (bn & (NWIN - 1)) * (NWIN_T * NWIN_T) + n * NWIN_T;
        const int r1 = n / WS, c1 = n - r1 * WS;

        float q[32];
        #pragma unroll
        for (int i = 0; i < 8; i++) {
            float4 v = *(const float4*)&Qs[n * 32 + i * 4];
            q[i*4+0] = v.x; q[i*4+1] = v.y; q[i*4+2] = v.z; q[i*4+3] = v.w;
        }

        for (int m = 0; m < NWIN_T; m++) {
            float acc = 0.0f;
            #pragma unroll
            for (int i = 0; i < 8; i++) {
                float4 kv = *(const float4*)&Ks[m * 32 + i * 4];
                acc += q[i*4+0]*kv.x + q[i*4+1]*kv.y + q[i*4+2]*kv.z + q[i*4+3]*kv.w;
            }
            int r2 = m / WS, c2 = m - r2 * WS;
            int rel = (r1 - r2 + WS - 1) * (2 * WS - 1) + (c1 - c2 + WS - 1);
            Ss[n * SST + m] = acc + rpb[rel * NHEADS + h] + mw[m];
        }

        float mx = -1e30f;
        for (int m = 0; m < NWIN_T; m++) mx = fmaxf(mx, Ss[n * SST + m]);
        float sum = 0.0f;
        for (int m = 0; m < NWIN_T; m++) {
            float e = __expf(Ss[n * SST + m] - mx);
            Ss[n * SST + m] = e; sum += e;
        }
        float inv = 1.0f / sum;

        float acc[32];
        #pragma unroll
        for (int i = 0; i < 32; i++) acc[i] = 0.0f;
        for (int m = 0; m < NWIN_T; m++) {
            float p = Ss[n * SST + m];
            #pragma unroll
            for (int i = 0; i < 8; i++) {
                float4 vv = *(const float4*)&Vs[m * 32 + i * 4];
                acc[i*4+0] += p * vv.x; acc[i*4+1] += p * vv.y;
                acc[i*4+2] += p * vv.z; acc[i*4+3] += p * vv.w;
            }
        }
        float* op = outp + (size_t)(bn * NWIN_T + n) * CDIM + h * HD;
        #pragma unroll
        for (int i = 0; i < 16; i++)
            *(float2*)(op + 2*i) = make_float2(tf32r(acc[2*i] * inv),
                                               tf32r(acc[2*i+1] * inv));
    }
}

// ---------------------------------------------------------------------------
// Launch
// ---------------------------------------------------------------------------
extern "C" void kernel_launch(void* const* d_in, const int* in_sizes, int n_in,
                              void* d_out, int out_size)
{
    const float* x        = (const float*)d_in[0];
    const float* attnmask = (const float*)d_in[1];
    const float* norm1_g  = (const float*)d_in[2];
    const float* norm1_b  = (const float*)d_in[3];
    const float* qkv_w    = (const float*)d_in[4];
    const float* qkv_b    = (const float*)d_in[5];
    const float* rpb      = (const float*)d_in[6];
    const float* proj_w   = (const float*)d_in[7];
    const float* proj_b   = (const float*)d_in[8];
    const float* norm2_g  = (const float*)d_in[9];
    const float* norm2_b  = (const float*)d_in[10];
    const float* fc1_w    = (const float*)d_in[11];
    const float* fc1_b    = (const float*)d_in[12];
    const float* fc2_w    = (const float*)d_in[13];
    const float* fc2_b    = (const float*)d_in[14];
    (void)in_sizes; (void)n_in; (void)out_size;

    float *qkvbuf, *projb, *y, *win, *att, *h2, *mlp, *wq, *wp, *w1, *w2;
    cudaGetSymbolAddress((void**)&qkvbuf, g_qkv);
    cudaGetSymbolAddress((void**)&projb,  g_proj);
    cudaGetSymbolAddress((void**)&y,      g_y);
    cudaGetSymbolAddress((void**)&win,    g_win);
    cudaGetSymbolAddress((void**)&att,    g_att);
    cudaGetSymbolAddress((void**)&h2,     g_h2);
    cudaGetSymbolAddress((void**)&mlp,    g_mlp);
    cudaGetSymbolAddress((void**)&wq,     g_wq);
    cudaGetSymbolAddress((void**)&wp,     g_wp);
    cudaGetSymbolAddress((void**)&w1,     g_w1);
    cudaGetSymbolAddress((void**)&w2,     g_w2);

    cudaFuncSetAttribute(mma_gemm<0>, cudaFuncAttributeMaxDynamicSharedMemorySize, GEMM_SMEM);
    cudaFuncSetAttribute(mma_gemm<1>, cudaFuncAttributeMaxDynamicSharedMemorySize, GEMM_SMEM);
    cudaFuncSetAttribute(mma_gemm<2>, cudaFuncAttributeMaxDynamicSharedMemorySize, GEMM_SMEM);

    // 0. weight transpose + tf32 round
    wtrans_kernel<<<dim3(3*CDIM/32, CDIM/32), 256>>>(qkv_w,  wq, CDIM, 3*CDIM);
    wtrans_kernel<<<dim3(CDIM/32,   CDIM/32), 256>>>(proj_w, wp, CDIM, CDIM);
    wtrans_kernel<<<dim3(HID/32,    CDIM/32), 256>>>(fc1_w,  w1, CDIM, HID);
    wtrans_kernel<<<dim3(CDIM/32,   HID/32),  256>>>(fc2_w,  w2, HID,  CDIM);

    // 1. LN1 + shift + window partition (tf32 fp32)
    ln1_kernel<<<MTOK, 128>>>(x, norm1_g, norm1_b, win);

    // 2. QKV GEMM (100352 x 384) @ (384 x 1152)
    mma_gemm<0><<<dim3(9, MTOK/128), 256, GEMM_SMEM>>>(
        win, wq, qkv_b, nullptr, qkvbuf, 3*CDIM, CDIM);

    // 3. Windowed attention (fp32 in, tf32 fp32 out)
    attn_kernel<<<dim3(BN, NHEADS), 64>>>(qkvbuf, attnmask, rpb, att);

    // 4. proj GEMM
    mma_gemm<0><<<dim3(3, MTOK/128), 256, GEMM_SMEM>>>(
        att, wp, proj_b, nullptr, projb, CDIM, CDIM);

    // 5+6. reverse + roll + residual + LN2 (fused)
    mergeln_kernel<<<MTOK, 128>>>(x, projb, norm2_g, norm2_b, y, h2);

    // 7. fc1 + GELU (tf32 fp32 out)
    mma_gemm<1><<<dim3(12, MTOK/128), 256, GEMM_SMEM>>>(
        h2, w1, fc1_b, nullptr, mlp, HID, CDIM);

    // 8. fc2 + residual -> d_out
    mma_gemm<2><<<dim3(3, MTOK/128), 256, GEMM_SMEM>>>(
        mlp, w2, fc2_b, y, (float*)d_out, CDIM, HID);
}

// round 11
// speedup vs baseline: 3.8756x; 1.4556x over previous
#include <cuda_runtime.h>
#include <cuda_fp16.h>
#include <math.h>
#include <stdint.h>

// ---------------------------------------------------------------------------
// Problem constants
// ---------------------------------------------------------------------------
#define BATCH   32
#define HIMG    56
#define WIMG    56
#define CDIM    384
#define LTOK    (HIMG*WIMG)          // 3136
#define NHEADS  12
#define HD      32
#define WS      7
#define NWIN_T  49
#define SHIFT   3
#define NWX     8
#define NWIN    64
#define BN      (BATCH*NWIN)         // 2048 windows
#define MTOK    (BN*NWIN_T)          // 100352 tokens
#define HID     1536

// ---------------------------------------------------------------------------
// Scratch (device globals)
// ---------------------------------------------------------------------------
__device__ float  g_qkv [(size_t)MTOK * 3 * CDIM];
__device__ float  g_proj[(size_t)MTOK * CDIM];
__device__ float  g_y   [(size_t)MTOK * CDIM];
__device__ __half g_win [(size_t)MTOK * CDIM];
__device__ __half g_att [(size_t)MTOK * CDIM];
__device__ __half g_h2  [(size_t)MTOK * CDIM];
__device__ __half g_mlp [(size_t)MTOK * HID];
// transposed weights Wt[N][K], fp16
__device__ __half g_wq[3*CDIM*CDIM];
__device__ __half g_wp[CDIM*CDIM];
__device__ __half g_w1[HID*CDIM];
__device__ __half g_w2[CDIM*HID];

// ---------------------------------------------------------------------------
// Helpers
// ---------------------------------------------------------------------------
static __device__ __forceinline__ uint32_t s2u(const void* p) {
    return (uint32_t)__cvta_generic_to_shared(p);
}
static __device__ __forceinline__ void ldm4(uint32_t& d0, uint32_t& d1, uint32_t& d2,
                                            uint32_t& d3, uint32_t a) {
    asm volatile("ldmatrix.sync.aligned.m8n8.x4.shared.b16 {%0,%1,%2,%3},[%4];"
                 : "=r"(d0), "=r"(d1), "=r"(d2), "=r"(d3) : "r"(a));
}
static __device__ __forceinline__ void mma_f16(float* c, const uint32_t* a, const uint32_t* b) {
    asm volatile("mma.sync.aligned.m16n8k16.row.col.f32.f16.f16.f32 "
                 "{%0,%1,%2,%3},{%4,%5,%6,%7},{%8,%9},{%0,%1,%2,%3};"
                 : "+f"(c[0]), "+f"(c[1]), "+f"(c[2]), "+f"(c[3])
                 : "r"(a[0]), "r"(a[1]), "r"(a[2]), "r"(a[3]), "r"(b[0]), "r"(b[1]));
}
static __device__ __forceinline__ void cpa16(uint32_t dst, const void* src) {
    asm volatile("cp.async.cg.shared.global [%0], [%1], 16;"
                 :: "r"(dst), "l"(src) : "memory");
}

// ---------------------------------------------------------------------------
// fp16 MMA GEMM: C[M,N] = A[M,K] @ B[N,K]^T, single pass, fp32 accumulate.
// 128x128 block tile, BK=32, 8 warps (2x4), warp tile 64x32.
// 64B smem rows (4 granules), swizzle g ^= (row>>1)&3.
// 4-stage cp.async (issue 3 ahead, wait_group 2), 2 CTAs/SM,
// one __syncthreads per chunk.
// EPI 0: fp32 + bias | 1: bias+GELU -> fp16 | 2: bias+residual -> fp32
// ---------------------------------------------------------------------------
#define TILE_B   (128*64)                 // 8192 bytes (128 rows x 64B)
#define STAGE_B  (2*TILE_B)               // A + B : 16384 bytes
#define NSTAGE   4
#define GEMM_SMEM (NSTAGE*STAGE_B)        // 65536 bytes

template <int EPI>
__global__ __launch_bounds__(256, 2)
void mma_gemm(const __half* __restrict__ A, const __half* __restrict__ B,
              const float* __restrict__ bias, const float* __restrict__ res,
              float* __restrict__ Cf, __half* __restrict__ Cm, int N, int K)
{
    extern __shared__ char sm[];
    const int tid  = threadIdx.x, lane = tid & 31, warp = tid >> 5;
    const int m0 = blockIdx.y * 128, n0 = blockIdx.x * 128;
    const int wm = (warp >> 2) * 64, wn = (warp & 3) * 32;

    // copy setup: thread owns row cr, granules g0 and g0+1 (16B = 8 halves each)
    const int cr = tid >> 1, g0 = (tid & 1) * 2;
    const __half* pA = A + (size_t)(m0 + cr) * K;
    const __half* pB = B + (size_t)(n0 + cr) * K;
    const uint32_t swc = ((uint32_t)cr >> 1) & 3;
    const uint32_t so0 = (uint32_t)cr * 64 + ((((uint32_t)g0    ) ^ swc) << 4);
    const uint32_t so1 = (uint32_t)cr * 64 + ((((uint32_t)g0 + 1) ^ swc) << 4);
    const uint32_t smb = s2u(sm);
    const int nch = K >> 5;

    auto issue_stage = [&](int i, int s) {
        int k0 = i << 5;
        uint32_t b = smb + (uint32_t)s * STAGE_B;
        cpa16(b + so0,          pA + k0 + g0 * 8);
        cpa16(b + so1,          pA + k0 + g0 * 8 + 8);
        cpa16(b + TILE_B + so0, pB + k0 + g0 * 8);
        cpa16(b + TILE_B + so1, pB + k0 + g0 * 8 + 8);
        asm volatile("cp.async.commit_group;" ::: "memory");
    };

    float acc[4][4][4];
    #pragma unroll
    for (int i = 0; i < 4; i++)
        #pragma unroll
        for (int j = 0; j < 4; j++)
            #pragma unroll
            for (int k = 0; k < 4; k++) acc[i][j][k] = 0.0f;

    // ldmatrix lane addressing
    const int tsel = lane >> 3, rlo = lane & 7;
    const uint32_t rA = (uint32_t)(wm + rlo + (tsel & 1) * 8);
    const uint32_t gA = (uint32_t)(tsel >> 1);
    const uint32_t rB = (uint32_t)(wn + rlo + (tsel >> 1) * 8);
    const uint32_t gB = (uint32_t)(tsel & 1);

    issue_stage(0, 0);
    if (nch > 1) issue_stage(1, 1);
    if (nch > 2) issue_stage(2, 2);

    int stage = 0;
    for (int i = 0; i < nch; i++) {
        int rem = nch - 1 - i;
        if (rem >= 2)      asm volatile("cp.async.wait_group 2;" ::: "memory");
        else if (rem == 1) asm volatile("cp.async.wait_group 1;" ::: "memory");
        else               asm volatile("cp.async.wait_group 0;" ::: "memory");
        __syncthreads();

        if (i + 3 < nch) {
            int s = stage + 3; if (s >= NSTAGE) s -= NSTAGE;
            issue_stage(i + 3, s);
        }

        const uint32_t sb = smb + (uint32_t)stage * STAGE_B;
        #pragma unroll
        for (int kst = 0; kst < 2; kst++) {
            uint32_t bfr[4][2];
            #pragma unroll
            for (int p = 0; p < 2; p++) {
                uint32_t row = rB + p * 16;
                uint32_t sw  = (row >> 1) & 3;
                uint32_t ad  = sb + TILE_B + row * 64 + (((gB + kst*2u) ^ sw) << 4);
                ldm4(bfr[2*p][0], bfr[2*p][1], bfr[2*p+1][0], bfr[2*p+1][1], ad);
            }
            #pragma unroll
            for (int mf = 0; mf < 4; mf++) {
                uint32_t row = rA + mf * 16;
                uint32_t sw  = (row >> 1) & 3;
                uint32_t ad  = sb + row * 64 + (((gA + kst*2u) ^ sw) << 4);
                uint32_t afr[4];
                ldm4(afr[0], afr[1], afr[2], afr[3], ad);
                #pragma unroll
                for (int nf = 0; nf < 4; nf++)
                    mma_f16(acc[mf][nf], afr, bfr[nf]);
            }
        }
        stage++; if (stage >= NSTAGE) stage = 0;
    }
    __syncthreads();

    // -- epilogue from accumulator fragments
    const int qr = lane >> 2, qc = (lane & 3) * 2;
    #pragma unroll
    for (int mf = 0; mf < 4; mf++) {
        int row = m0 + wm + mf * 16 + qr;
        #pragma unroll
        for (int nf = 0; nf < 4; nf++) {
            int col = n0 + wn + nf * 8 + qc;
            float b0 = bias[col], b1 = bias[col + 1];
            float v0 = acc[mf][nf][0] + b0, v1 = acc[mf][nf][1] + b1;
            float v2 = acc[mf][nf][2] + b0, v3 = acc[mf][nf][3] + b1;
            if (EPI == 0) {
                *(float2*)(Cf + (size_t)row * N + col)       = make_float2(v0, v1);
                *(float2*)(Cf + (size_t)(row + 8) * N + col) = make_float2(v2, v3);
            } else if (EPI == 1) {
                v0 = 0.5f * v0 * (1.0f + erff(v0 * 0.70710678118654752f));
                v1 = 0.5f * v1 * (1.0f + erff(v1 * 0.70710678118654752f));
                v2 = 0.5f * v2 * (1.0f + erff(v2 * 0.70710678118654752f));
                v3 = 0.5f * v3 * (1.0f + erff(v3 * 0.70710678118654752f));
                *(__half2*)(Cm + (size_t)row * N + col)       = __floats2half2_rn(v0, v1);
                *(__half2*)(Cm + (size_t)(row + 8) * N + col) = __floats2half2_rn(v2, v3);
            } else {
                float2 r0v = *(const float2*)(res + (size_t)row * N + col);
                float2 r1v = *(const float2*)(res + (size_t)(row + 8) * N + col);
                *(float2*)(Cf + (size_t)row * N + col)       = make_float2(v0 + r0v.x, v1 + r0v.y);
                *(float2*)(Cf + (size_t)(row + 8) * N + col) = make_float2(v2 + r1v.x, v3 + r1v.y);
            }
        }
    }
}

// ---------------------------------------------------------------------------
// Weight transpose + fp16 round: W[K][N] fp32 -> Wt[N][K] fp16
// ---------------------------------------------------------------------------
__global__ __launch_bounds__(256)
void wtrans_kernel(const float* __restrict__ W, __half* __restrict__ Wt, int K, int N)
{
    __shared__ float t[32][33];
    int tx = threadIdx.x & 31, ty = threadIdx.x >> 5;   // 32 x 8
    int kb = blockIdx.y * 32, nb = blockIdx.x * 32;
    #pragma unroll
    for (int j = ty; j < 32; j += 8)
        t[j][tx] = W[(size_t)(kb + j) * N + nb + tx];
    __syncthreads();
    #pragma unroll
    for (int j = ty; j < 32; j += 8)
        Wt[(size_t)(nb + j) * K + kb + tx] = __float2half_rn(t[tx][j]);
}

// ---------------------------------------------------------------------------
// LN1 + shift + window-partition gather -> fp16
// ---------------------------------------------------------------------------
__global__ __launch_bounds__(128)
void ln1_kernel(const float* __restrict__ x, const float* __restrict__ gam,
                const float* __restrict__ bet, __half* __restrict__ out)
{
    int tr = blockIdx.x;
    int bn = tr / NWIN_T;
    int n  = tr - bn * NWIN_T;
    int b  = bn / NWIN;
    int wi = bn - b * NWIN;
    int wy = wi / NWX, wx = wi - wy * NWX;
    int r  = n / WS,   cc = n - r * WS;
    int hs = (wy * WS + r  + SHIFT) % HIMG;
    int ws2= (wx * WS + cc + SHIFT) % WIMG;
    int src = b * LTOK + hs * WIMG + ws2;

    const float* xin = x + (size_t)src * CDIM;
    int tid = threadIdx.x;
    float v0 = xin[tid], v1 = xin[tid + 128], v2 = xin[tid + 256];
    float s  = v0 + v1 + v2;
    float ss = v0*v0 + v1*v1 + v2*v2;
    #pragma unroll
    for (int o = 16; o > 0; o >>= 1) {
        s  += __shfl_down_sync(0xffffffffu, s,  o);
        ss += __shfl_down_sync(0xffffffffu, ss, o);
    }
    __shared__ float red[8];
    __shared__ float mbv[2];
    int w = tid >> 5, l = tid & 31;
    if (l == 0) { red[w] = s; red[4 + w] = ss; }
    __syncthreads();
    if (tid == 0) {
        float S  = red[0] + red[1] + red[2] + red[3];
        float SS = red[4] + red[5] + red[6] + red[7];
        float mean = S * (1.0f / CDIM);
        float var  = SS * (1.0f / CDIM) - mean * mean;
        mbv[0] = mean; mbv[1] = rsqrtf(var + 1e-5f);
    }
    __syncthreads();
    float mean = mbv[0], rstd = mbv[1];
    __half* o = out + (size_t)tr * CDIM;
    o[tid]       = __float2half_rn((v0 - mean) * rstd * gam[tid]       + bet[tid]);
    o[tid + 128] = __float2half_rn((v1 - mean) * rstd * gam[tid + 128] + bet[tid + 128]);
    o[tid + 256] = __float2half_rn((v2 - mean) * rstd * gam[tid + 256] + bet[tid + 256]);
}

// ---------------------------------------------------------------------------
// Fused: window-reverse + roll + residual (y exact fp32), then LN2 -> fp16
// ---------------------------------------------------------------------------
__global__ __launch_bounds__(128)
void mergeln_kernel(const float* __restrict__ x, const float* __restrict__ proj,
                    const float* __restrict__ gam, const float* __restrict__ bet,
                    float* __restrict__ y, __half* __restrict__ out)
{
    int tr = blockIdx.x;
    int b = tr / LTOK, pos = tr - b * LTOK;
    int i = pos / WIMG, j = pos - i * WIMG;
    int ii = (i + HIMG - SHIFT) % HIMG;
    int jj = (j + WIMG - SHIFT) % WIMG;
    int wr = (b * NWIN + (ii / WS) * NWX + (jj / WS)) * NWIN_T + (ii % WS) * WS + (jj % WS);

    const float* xp = x    + (size_t)tr * CDIM;
    const float* pp = proj + (size_t)wr * CDIM;
    int tid = threadIdx.x;
    float v0 = xp[tid]       + pp[tid];
    float v1 = xp[tid + 128] + pp[tid + 128];
    float v2 = xp[tid + 256] + pp[tid + 256];

    float* yp = y + (size_t)tr * CDIM;
    yp[tid] = v0; yp[tid + 128] = v1; yp[tid + 256] = v2;

    float s  = v0 + v1 + v2;
    float ss = v0*v0 + v1*v1 + v2*v2;
    #pragma unroll
    for (int o = 16; o > 0; o >>= 1) {
        s  += __shfl_down_sync(0xffffffffu, s,  o);
        ss += __shfl_down_sync(0xffffffffu, ss, o);
    }
    __shared__ float red[8];
    __shared__ float mbv[2];
    int w = tid >> 5, l = tid & 31;
    if (l == 0) { red[w] = s; red[4 + w] = ss; }
    __syncthreads();
    if (tid == 0) {
        float S  = red[0] + red[1] + red[2] + red[3];
        float SS = red[4] + red[5] + red[6] + red[7];
        float mean = S * (1.0f / CDIM);
        float var  = SS * (1.0f / CDIM) - mean * mean;
        mbv[0] = mean; mbv[1] = rsqrtf(var + 1e-5f);
    }
    __syncthreads();
    float mean = mbv[0], rstd = mbv[1];
    __half* o = out + (size_t)tr * CDIM;
    o[tid]       = __float2half_rn((v0 - mean) * rstd * gam[tid]       + bet[tid]);
    o[tid + 128] = __float2half_rn((v1 - mean) * rstd * gam[tid + 128] + bet[tid + 128]);
    o[tid + 256] = __float2half_rn((v2 - mean) * rstd * gam[tid + 256] + bet[tid + 256]);
}

// ---------------------------------------------------------------------------
// Windowed attention: one block (64 thr) per (window, head).
// Thread n keeps Q row / output row in registers; K/V via broadcast LDS.128.
// Output fp16.
// ---------------------------------------------------------------------------
#define SST 50   // padded logits stride
__global__ __launch_bounds__(64)
void attn_kernel(const float* __restrict__ qkv, const float* __restrict__ mask,
                 const float* __restrict__ rpb, __half* __restrict__ outp)
{
    __shared__ float Qs[NWIN_T * 32];
    __shared__ float Ks[NWIN_T * 32];
    __shared__ float Vs[NWIN_T * 32];
    __shared__ float Ss[NWIN_T * SST];

    int bn = blockIdx.x, h = blockIdx.y, tid = threadIdx.x;
    const float scale = 0.1767766952966369f;   // 32^-0.5

    size_t basep = (size_t)bn * NWIN_T * (3 * CDIM) + h * HD;
    for (int idx = tid; idx < NWIN_T * 8; idx += 64) {
        int n = idx >> 3, q = idx & 7;
        const float* rowp = qkv + basep + (size_t)n * (3 * CDIM);
        float4 qv = *(const float4*)(rowp + q * 4);
        qv.x *= scale; qv.y *= scale; qv.z *= scale; qv.w *= scale;
        *(float4*)&Qs[n * 32 + q * 4] = qv;
        *(float4*)&Ks[n * 32 + q * 4] = *(const float4*)(rowp + CDIM + q * 4);
        *(float4*)&Vs[n * 32 + q * 4] = *(const float4*)(rowp + 2 * CDIM + q * 4);
    }
    __syncthreads();

    if (tid < NWIN_T) {
        const int n = tid;
        const float* mw = mask + (bn & (NWIN - 1)) * (NWIN_T * NWIN_T) + n * NWIN_T;
        const int r1 = n / WS, c1 = n - r1 * WS;

        float q[32];
        #pragma unroll
        for (int i = 0; i < 8; i++) {
            float4 v = *(const float4*)&Qs[n * 32 + i * 4];
            q[i*4+0] = v.x; q[i*4+1] = v.y; q[i*4+2] = v.z; q[i*4+3] = v.w;
        }

        for (int m = 0; m < NWIN_T; m++) {
            float acc = 0.0f;
            #pragma unroll
            for (int i = 0; i < 8; i++) {
                float4 kv = *(const float4*)&Ks[m * 32 + i * 4];
                acc += q[i*4+0]*kv.x + q[i*4+1]*kv.y + q[i*4+2]*kv.z + q[i*4+3]*kv.w;
            }
            int r2 = m / WS, c2 = m - r2 * WS;
            int rel = (r1 - r2 + WS - 1) * (2 * WS - 1) + (c1 - c2 + WS - 1);
            Ss[n * SST + m] = acc + rpb[rel * NHEADS + h] + mw[m];
        }

        float mx = -1e30f;
        for (int m = 0; m < NWIN_T; m++) mx = fmaxf(mx, Ss[n * SST + m]);
        float sum = 0.0f;
        for (int m = 0; m < NWIN_T; m++) {
            float e = __expf(Ss[n * SST + m] - mx);
            Ss[n * SST + m] = e; sum += e;
        }
        float inv = 1.0f / sum;

        float acc[32];
        #pragma unroll
        for (int i = 0; i < 32; i++) acc[i] = 0.0f;
        for (int m = 0; m < NWIN_T; m++) {
            float p = Ss[n * SST + m];
            #pragma unroll
            for (int i = 0; i < 8; i++) {
                float4 vv = *(const float4*)&Vs[m * 32 + i * 4];
                acc[i*4+0] += p * vv.x; acc[i*4+1] += p * vv.y;
                acc[i*4+2] += p * vv.z; acc[i*4+3] += p * vv.w;
            }
        }
        __half* op = outp + (size_t)(bn * NWIN_T + n) * CDIM + h * HD;
        #pragma unroll
        for (int i = 0; i < 16; i++)
            *(__half2*)(op + 2*i) = __floats2half2_rn(acc[2*i] * inv, acc[2*i+1] * inv);
    }
}

// ---------------------------------------------------------------------------
// Launch
// ---------------------------------------------------------------------------
extern "C" void kernel_launch(void* const* d_in, const int* in_sizes, int n_in,
                              void* d_out, int out_size)
{
    const float* x        = (const float*)d_in[0];
    const float* attnmask = (const float*)d_in[1];
    const float* norm1_g  = (const float*)d_in[2];
    const float* norm1_b  = (const float*)d_in[3];
    const float* qkv_w    = (const float*)d_in[4];
    const float* qkv_b    = (const float*)d_in[5];
    const float* rpb      = (const float*)d_in[6];
    const float* proj_w   = (const float*)d_in[7];
    const float* proj_b   = (const float*)d_in[8];
    const float* norm2_g  = (const float*)d_in[9];
    const float* norm2_b  = (const float*)d_in[10];
    const float* fc1_w    = (const float*)d_in[11];
    const float* fc1_b    = (const float*)d_in[12];
    const float* fc2_w    = (const float*)d_in[13];
    const float* fc2_b    = (const float*)d_in[14];
    (void)in_sizes; (void)n_in; (void)out_size;

    float *qkvbuf, *projb, *y;
    __half *win, *att, *h2, *mlp, *wq, *wp, *w1, *w2;
    cudaGetSymbolAddress((void**)&qkvbuf, g_qkv);
    cudaGetSymbolAddress((void**)&projb,  g_proj);
    cudaGetSymbolAddress((void**)&y,      g_y);
    cudaGetSymbolAddress((void**)&win,    g_win);
    cudaGetSymbolAddress((void**)&att,    g_att);
    cudaGetSymbolAddress((void**)&h2,     g_h2);
    cudaGetSymbolAddress((void**)&mlp,    g_mlp);
    cudaGetSymbolAddress((void**)&wq,     g_wq);
    cudaGetSymbolAddress((void**)&wp,     g_wp);
    cudaGetSymbolAddress((void**)&w1,     g_w1);
    cudaGetSymbolAddress((void**)&w2,     g_w2);

    cudaFuncSetAttribute(mma_gemm<0>, cudaFuncAttributeMaxDynamicSharedMemorySize, GEMM_SMEM);
    cudaFuncSetAttribute(mma_gemm<1>, cudaFuncAttributeMaxDynamicSharedMemorySize, GEMM_SMEM);
    cudaFuncSetAttribute(mma_gemm<2>, cudaFuncAttributeMaxDynamicSharedMemorySize, GEMM_SMEM);

    // 0. weight transpose + fp16 round
    wtrans_kernel<<<dim3(3*CDIM/32, CDIM/32), 256>>>(qkv_w,  wq, CDIM, 3*CDIM);
    wtrans_kernel<<<dim3(CDIM/32,   CDIM/32), 256>>>(proj_w, wp, CDIM, CDIM);
    wtrans_kernel<<<dim3(HID/32,    CDIM/32), 256>>>(fc1_w,  w1, CDIM, HID);
    wtrans_kernel<<<dim3(CDIM/32,   HID/32),  256>>>(fc2_w,  w2, HID,  CDIM);

    // 1. LN1 + shift + window partition (fp16)
    ln1_kernel<<<MTOK, 128>>>(x, norm1_g, norm1_b, win);

    // 2. QKV GEMM (100352 x 384) @ (384 x 1152)
    mma_gemm<0><<<dim3(9, MTOK/128), 256, GEMM_SMEM>>>(
        win, wq, qkv_b, nullptr, qkvbuf, nullptr, 3*CDIM, CDIM);

    // 3. Windowed attention (fp32 in, fp16 out)
    attn_kernel<<<dim3(BN, NHEADS), 64>>>(qkvbuf, attnmask, rpb, att);

    // 4. proj GEMM
    mma_gemm<0><<<dim3(3, MTOK/128), 256, GEMM_SMEM>>>(
        att, wp, proj_b, nullptr, projb, nullptr, CDIM, CDIM);

    // 5+6. reverse + roll + residual + LN2 (fused)
    mergeln_kernel<<<MTOK, 128>>>(x, projb, norm2_g, norm2_b, y, h2);

    // 7. fc1 + GELU (fp16 out)
    mma_gemm<1><<<dim3(12, MTOK/128), 256, GEMM_SMEM>>>(
        h2, w1, fc1_b, nullptr, nullptr, mlp, HID, CDIM);

    // 8. fc2 + residual -> d_out
    mma_gemm<2><<<dim3(3, MTOK/128), 256, GEMM_SMEM>>>(
        mlp, w2, fc2_b, y, (float*)d_out, nullptr, CDIM, HID);
}